// round 2
// baseline (speedup 1.0000x reference)
#include <cuda_runtime.h>

// Problem constants
#define Bc    4
#define Mc    4096
#define HIDc  1024
#define Hc    16
#define HDc   64
#define SEGc  128
#define NSEGc 32
#define SCALEc 0.125f   // HD^-0.5 = 64^-0.5

// Scratch (static __device__ — allocation-free per harness rules)
// g_qkv layout: [c(3)][b][h][m][d], m = ORIGINAL token index (pre-gather)
__device__ float g_qkv[(size_t)3 * Bc * Hc * Mc * HDc];   // 192 MB
// g_attn layout: [b][i][h*64+d], i = HILBERT position (reference never un-permutes)
__device__ float g_attn[(size_t)Bc * Mc * HIDc];          // 64 MB

// ---------------------------------------------------------------------------
// Classic SGEMM: C[row][col] = sum_k A[row][k] * W[col][k]   (W row-major [N][K])
// 128x128 tile, BK=8, 256 threads, 8x8 per-thread register tile.
// MODE 0: epilogue scatters into g_qkv [c][b][h][m][d] layout.
// MODE 1: A is ignored (reads g_attn), epilogue writes plain row-major Cout.
// ---------------------------------------------------------------------------
template <int MODE>
__global__ __launch_bounds__(256) void sgemm_kernel(const float* __restrict__ A,
                                                    const float* __restrict__ W,
                                                    float* __restrict__ Cout) {
    const int K = HIDc;
    __shared__ float As[8][128];
    __shared__ float Bs[8][128];

    const int tid  = threadIdx.x;
    const int row0 = blockIdx.y * 128;
    const int col0 = blockIdx.x * 128;

    const float* Abase = (MODE == 1) ? g_attn : A;

    const int lr = tid >> 1;         // 0..127
    const int lk = (tid & 1) * 4;    // 0 or 4
    const float* Aptr = Abase + (size_t)(row0 + lr) * K + lk;
    const float* Bptr = W     + (size_t)(col0 + lr) * K + lk;

    const int ty = tid >> 4;   // 0..15
    const int tx = tid & 15;   // 0..15

    float acc[8][8];
#pragma unroll
    for (int i = 0; i < 8; i++)
#pragma unroll
        for (int j = 0; j < 8; j++) acc[i][j] = 0.0f;

    for (int k0 = 0; k0 < K; k0 += 8) {
        float4 av = *(const float4*)(Aptr + k0);
        float4 bv = *(const float4*)(Bptr + k0);
        As[lk + 0][lr] = av.x; As[lk + 1][lr] = av.y;
        As[lk + 2][lr] = av.z; As[lk + 3][lr] = av.w;
        Bs[lk + 0][lr] = bv.x; Bs[lk + 1][lr] = bv.y;
        Bs[lk + 2][lr] = bv.z; Bs[lk + 3][lr] = bv.w;
        __syncthreads();

#pragma unroll
        for (int kk = 0; kk < 8; kk++) {
            float af[8], bf[8];
#pragma unroll
            for (int i = 0; i < 8; i++) af[i] = As[kk][ty * 8 + i];
#pragma unroll
            for (int j = 0; j < 8; j++) bf[j] = Bs[kk][tx * 8 + j];
#pragma unroll
            for (int i = 0; i < 8; i++)
#pragma unroll
                for (int j = 0; j < 8; j++) acc[i][j] += af[i] * bf[j];
        }
        __syncthreads();
    }

    // Epilogue
#pragma unroll
    for (int i = 0; i < 8; i++) {
        const int r = row0 + ty * 8 + i;          // global row = b*M + m
#pragma unroll
        for (int j = 0; j < 8; j++) {
            const int c = col0 + tx * 8 + j;
            if (MODE == 0) {
                // c over 3072: c = cc*1024 + h*64 + d
                const int b  = r >> 12;           // /4096
                const int m  = r & 4095;
                const int cc = c >> 10;
                const int rem = c & 1023;
                const int h  = rem >> 6;
                const int d  = rem & 63;
                g_qkv[((((size_t)cc * Bc + b) * Hc + h) * Mc + m) * HDc + d] = acc[i][j];
            } else {
                Cout[(size_t)r * HIDc + c] = acc[i][j];
            }
        }
    }
}

// ---------------------------------------------------------------------------
// Attention: one block per (seg, h, b). Q/K/V tiles gathered via hilbert map
// into padded SMEM. Q/K use stride 65 (conflict-free scalar K-row access);
// V uses stride 66 (EVEN -> float2 reads are 8-byte aligned).
// 8 warps, each warp owns 16 query rows, warp-local softmax.
// ---------------------------------------------------------------------------
#define LDP  65
#define LDPV 66
#define SMEM_ATTN ((2 * 128 * LDP + 128 * LDPV + 8 * 128) * (int)sizeof(float))

__global__ __launch_bounds__(256) void attn_kernel(const int* __restrict__ hmap) {
    const int seg = blockIdx.x;
    const int h   = blockIdx.y;
    const int b   = blockIdx.z;

    extern __shared__ float sm[];
    float* Qs = sm;                    // 128 * 65
    float* Ks = Qs + 128 * LDP;        // 128 * 65
    float* Vs = Ks + 128 * LDP;        // 128 * 66 (even stride, 8B-aligned rows)
    float* Ps = Vs + 128 * LDPV;       // 8 * 128 (per-warp softmax probs)
    __shared__ int toks[128];

    const int tid = threadIdx.x;

    if (tid < 128) toks[tid] = hmap[seg * 128 + tid];
    __syncthreads();

    const size_t base_q = (((size_t)0 * Bc + b) * Hc + h) * (size_t)Mc * HDc;
    const size_t base_k = (((size_t)1 * Bc + b) * Hc + h) * (size_t)Mc * HDc;
    const size_t base_v = (((size_t)2 * Bc + b) * Hc + h) * (size_t)Mc * HDc;

    // Gathered tile loads: consecutive tid -> consecutive d (coalesced per row)
    for (int i = tid; i < 128 * 64; i += 256) {
        const int row = i >> 6;
        const int d   = i & 63;
        const size_t off = (size_t)toks[row] * HDc + d;
        Qs[row * LDP  + d] = g_qkv[base_q + off];
        Ks[row * LDP  + d] = g_qkv[base_k + off];
        Vs[row * LDPV + d] = g_qkv[base_v + off];
    }
    __syncthreads();

    const int warp = tid >> 5;
    const int lane = tid & 31;

    for (int r = 0; r < 16; r++) {
        const int s = warp * 16 + r;
        const bool row_active = ((s & 1) == 0);   // DIL = 2

        // scores: lane computes t = lane + 32*j
        float sc[4] = {0.f, 0.f, 0.f, 0.f};
#pragma unroll 8
        for (int d = 0; d < 64; d++) {
            const float qd = Qs[s * LDP + d];
#pragma unroll
            for (int j = 0; j < 4; j++)
                sc[j] += qd * Ks[(lane + 32 * j) * LDP + d];
        }

        float mx = -1e30f;
#pragma unroll
        for (int j = 0; j < 4; j++) {
            const int t = lane + 32 * j;
            const bool ok = row_active || ((t & 1) == 0);
            sc[j] = ok ? sc[j] * SCALEc : -1e30f;
            mx = fmaxf(mx, sc[j]);
        }
#pragma unroll
        for (int o = 16; o > 0; o >>= 1)
            mx = fmaxf(mx, __shfl_xor_sync(0xffffffffu, mx, o));

        float sum = 0.f;
#pragma unroll
        for (int j = 0; j < 4; j++) {
            sc[j] = __expf(sc[j] - mx);           // masked -> exp(~-1e30) = 0
            sum += sc[j];
        }
#pragma unroll
        for (int o = 16; o > 0; o >>= 1)
            sum += __shfl_xor_sync(0xffffffffu, sum, o);
        const float inv = 1.0f / sum;

#pragma unroll
        for (int j = 0; j < 4; j++)
            Ps[warp * 128 + lane + 32 * j] = sc[j] * inv;
        __syncwarp();

        // out: lane computes d = 2*lane, 2*lane+1 (vectorized, 8B-aligned V reads)
        float o0 = 0.f, o1 = 0.f;
#pragma unroll 4
        for (int t = 0; t < 128; t++) {
            const float p = Ps[warp * 128 + t];
            const float2 v2 = *(const float2*)&Vs[t * LDPV + 2 * lane];
            o0 += p * v2.x;
            o1 += p * v2.y;
        }

        const size_t orow = ((size_t)b * Mc + (size_t)seg * 128 + s) * HIDc + h * 64;
        g_attn[orow + 2 * lane]     = o0;
        g_attn[orow + 2 * lane + 1] = o1;
        __syncwarp();
    }
}

// ---------------------------------------------------------------------------
extern "C" void kernel_launch(void* const* d_in, const int* in_sizes, int n_in,
                              void* d_out, int out_size) {
    const float* x     = (const float*)d_in[0];
    const float* w_qkv = (const float*)d_in[1];
    const float* w_out = (const float*)d_in[2];
    const int*   hmap  = (const int*)d_in[3];
    float*       out   = (float*)d_out;

    cudaFuncSetAttribute(attn_kernel,
                         cudaFuncAttributeMaxDynamicSharedMemorySize, SMEM_ATTN);

    // QKV projection: 16384 x 3072 x 1024
    {
        dim3 grid(3072 / 128, (Bc * Mc) / 128);   // (24, 128)
        sgemm_kernel<0><<<grid, 256>>>(x, w_qkv, nullptr);
    }
    // Hilbert-gathered segmented attention
    {
        dim3 grid(NSEGc, Hc, Bc);                 // (32, 16, 4)
        attn_kernel<<<grid, 256, SMEM_ATTN>>>(hmap);
    }
    // Output projection: 16384 x 1024 x 1024
    {
        dim3 grid(HIDc / 128, (Bc * Mc) / 128);   // (8, 128)
        sgemm_kernel<1><<<grid, 256>>>(nullptr, w_out, out);
    }
}

// round 4
// speedup vs baseline: 2.2546x; 2.2546x over previous
#include <cuda_runtime.h>
#include <cuda_bf16.h>
#include <cstdint>

// Problem constants
#define Bc    4
#define Mc    4096
#define HIDc  1024
#define Hc    16
#define HDc   64
#define NSEGc 32
#define SCALEc 0.125f

// Scratch (static __device__ — allocation-free per harness rules)
__device__ float g_qkv[(size_t)3 * Bc * Hc * Mc * HDc];   // [c][b][h][m][d]
__device__ float g_attn[(size_t)Bc * Mc * HIDc];          // [b][hilbert_i][h*64+d]

// ===========================================================================
// Warp-MMA helpers (sm_80-class instructions: valid on plain compute_103)
// ===========================================================================
__device__ __forceinline__ uint32_t smem_u32(const void* p) {
    uint32_t a;
    asm("{ .reg .u64 t; cvta.to.shared.u64 t, %1; cvt.u32.u64 %0, t; }"
        : "=r"(a) : "l"(p));
    return a;
}

__device__ __forceinline__ void ldsm_x4(uint32_t* r, uint32_t addr) {
    asm volatile("ldmatrix.sync.aligned.m8n8.x4.shared.b16 {%0,%1,%2,%3}, [%4];"
                 : "=r"(r[0]), "=r"(r[1]), "=r"(r[2]), "=r"(r[3]) : "r"(addr));
}

__device__ __forceinline__ void mma_bf16(float* c, const uint32_t* a,
                                         uint32_t b0, uint32_t b1) {
    asm volatile(
        "mma.sync.aligned.m16n8k16.row.col.f32.bf16.bf16.f32 "
        "{%0,%1,%2,%3}, {%4,%5,%6,%7}, {%8,%9}, {%0,%1,%2,%3};"
        : "+f"(c[0]), "+f"(c[1]), "+f"(c[2]), "+f"(c[3])
        : "r"(a[0]), "r"(a[1]), "r"(a[2]), "r"(a[3]), "r"(b0), "r"(b1));
}

// Split (x,y) into packed bf16 hi pair and lo pair (3-term compensation basis)
__device__ __forceinline__ void split2(float x, float y, uint32_t& hi, uint32_t& lo) {
    __nv_bfloat16 hx = __float2bfloat16_rn(x);
    __nv_bfloat16 hy = __float2bfloat16_rn(y);
    __nv_bfloat16 lx = __float2bfloat16_rn(x - __bfloat162float(hx));
    __nv_bfloat16 ly = __float2bfloat16_rn(y - __bfloat162float(hy));
    __nv_bfloat162 H = __halves2bfloat162(hx, hy);
    __nv_bfloat162 L = __halves2bfloat162(lx, ly);
    hi = *reinterpret_cast<uint32_t*>(&H);
    lo = *reinterpret_cast<uint32_t*>(&L);
}

// ===========================================================================
// bf16x3 tensor GEMM: C[row][col] = sum_k A[row][k] * W[col][k]
// 128x128 tile, K-chunk 32, 256 threads, warp grid 4(m) x 2(n), warp tile 32x64.
// SMEM: 4 bf16 tiles [128][40] (stride 40 elems = 80B, ldmatrix conflict-free).
// MODE 0: epilogue scatters into g_qkv;  MODE 1: A<-g_attn, row-major out.
// ===========================================================================
#define TK      32
#define NITER   (HIDc / TK)     // 32
#define LDS_STRIDE 40           // bf16 elements per row (80 bytes)
#define TILE_HB (128 * LDS_STRIDE * 2)  // 10240 bytes per bf16 tile

template <int MODE>
__global__ __launch_bounds__(256, 2) void tgemm_kernel(const float* __restrict__ A,
                                                       const float* __restrict__ W,
                                                       float* __restrict__ Cout) {
    __shared__ __align__(16) __nv_bfloat16 smem_tiles[4 * 128 * LDS_STRIDE];
    const uint32_t smb = smem_u32(smem_tiles);
    const uint32_t AHI = smb;
    const uint32_t ALO = smb + TILE_HB;
    const uint32_t BHI = smb + 2 * TILE_HB;
    const uint32_t BLO = smb + 3 * TILE_HB;

    const int tid  = threadIdx.x;
    const int wid  = tid >> 5;
    const int lane = tid & 31;
    const int row0 = blockIdx.y * 128;
    const int col0 = blockIdx.x * 128;
    const int warp_m = wid & 3;       // 4 warps over M (32 rows each)
    const int warp_n = wid >> 2;      // 2 warps over N (64 cols each)

    const float* Abase = (MODE == 1) ? g_attn : A;

    // ---- global load mapping: thread handles 4 (row, 16B-chunk) pairs ----
    const float* ap[4]; const float* bp[4]; uint32_t sto[4];
    #pragma unroll
    for (int t = 0; t < 4; t++) {
        const int ci  = tid + 256 * t;
        const int row = ci >> 3;         // 0..127
        const int c16 = ci & 7;          // 0..7 (float4 index in 32-float row)
        ap[t]  = Abase + (size_t)(row0 + row) * HIDc + c16 * 4;
        bp[t]  = W     + (size_t)(col0 + row) * HIDc + c16 * 4;
        sto[t] = (uint32_t)(row * (LDS_STRIDE * 2) + c16 * 8);  // byte offset
    }

    // ---- ldmatrix address bases (lane-dependent) ----
    const int sub = lane >> 3;
    const int r8  = lane & 7;
    uint32_t a_lm[2], b_lm[4];
    #pragma unroll
    for (int mt = 0; mt < 2; mt++) {
        const int row  = warp_m * 32 + mt * 16 + (sub & 1) * 8 + r8;
        const int kbyt = (sub >> 1) * 16;
        a_lm[mt] = AHI + row * (LDS_STRIDE * 2) + kbyt;
    }
    #pragma unroll
    for (int np = 0; np < 4; np++) {
        const int row  = warp_n * 64 + np * 16 + (sub >> 1) * 8 + r8;
        const int kbyt = (sub & 1) * 16;
        b_lm[np] = BHI + row * (LDS_STRIDE * 2) + kbyt;
    }

    float acc[2][8][4];
    #pragma unroll
    for (int i = 0; i < 2; i++)
        #pragma unroll
        for (int j = 0; j < 8; j++)
            #pragma unroll
            for (int q = 0; q < 4; q++) acc[i][j][q] = 0.0f;

    float4 ra[4], rb[4];
    #pragma unroll
    for (int t = 0; t < 4; t++) { ra[t] = *(const float4*)(ap[t]); rb[t] = *(const float4*)(bp[t]); }

    for (int it = 0; it < NITER; it++) {
        // ---- split to bf16 hi/lo and store to SMEM ----
        #pragma unroll
        for (int t = 0; t < 4; t++) {
            uint32_t ah0, al0, ah1, al1, bh0, bl0, bh1, bl1;
            split2(ra[t].x, ra[t].y, ah0, al0);
            split2(ra[t].z, ra[t].w, ah1, al1);
            split2(rb[t].x, rb[t].y, bh0, bl0);
            split2(rb[t].z, rb[t].w, bh1, bl1);
            asm volatile("st.shared.v2.b32 [%0], {%1,%2};" :: "r"(AHI + sto[t]), "r"(ah0), "r"(ah1) : "memory");
            asm volatile("st.shared.v2.b32 [%0], {%1,%2};" :: "r"(ALO + sto[t]), "r"(al0), "r"(al1) : "memory");
            asm volatile("st.shared.v2.b32 [%0], {%1,%2};" :: "r"(BHI + sto[t]), "r"(bh0), "r"(bh1) : "memory");
            asm volatile("st.shared.v2.b32 [%0], {%1,%2};" :: "r"(BLO + sto[t]), "r"(bl0), "r"(bl1) : "memory");
        }
        __syncthreads();

        // ---- prefetch next chunk (lands while MMAs run) ----
        if (it + 1 < NITER) {
            const int k0 = (it + 1) * TK;
            #pragma unroll
            for (int t = 0; t < 4; t++) {
                ra[t] = *(const float4*)(ap[t] + k0);
                rb[t] = *(const float4*)(bp[t] + k0);
            }
        }

        // ---- MMA phase: 2 k16-steps, 3 compensation terms ----
        #pragma unroll
        for (int k16 = 0; k16 < 2; k16++) {
            const uint32_t kb = k16 * 32;
            uint32_t Ah[2][4], Al[2][4], Bf[4][4];
            #pragma unroll
            for (int mt = 0; mt < 2; mt++) {
                ldsm_x4(Ah[mt], a_lm[mt] + kb);
                ldsm_x4(Al[mt], a_lm[mt] + kb + (uint32_t)TILE_HB);  // ALO
            }
            #pragma unroll
            for (int np = 0; np < 4; np++) ldsm_x4(Bf[np], b_lm[np] + kb);  // BHI
            // Ah*Bh and Al*Bh
            #pragma unroll
            for (int mt = 0; mt < 2; mt++)
                #pragma unroll
                for (int np = 0; np < 4; np++) {
                    mma_bf16(acc[mt][2 * np],     Ah[mt], Bf[np][0], Bf[np][1]);
                    mma_bf16(acc[mt][2 * np + 1], Ah[mt], Bf[np][2], Bf[np][3]);
                    mma_bf16(acc[mt][2 * np],     Al[mt], Bf[np][0], Bf[np][1]);
                    mma_bf16(acc[mt][2 * np + 1], Al[mt], Bf[np][2], Bf[np][3]);
                }
            // Ah*Bl
            #pragma unroll
            for (int np = 0; np < 4; np++) ldsm_x4(Bf[np], b_lm[np] + kb + (uint32_t)TILE_HB);  // BLO
            #pragma unroll
            for (int mt = 0; mt < 2; mt++)
                #pragma unroll
                for (int np = 0; np < 4; np++) {
                    mma_bf16(acc[mt][2 * np],     Ah[mt], Bf[np][0], Bf[np][1]);
                    mma_bf16(acc[mt][2 * np + 1], Ah[mt], Bf[np][2], Bf[np][3]);
                }
        }
        __syncthreads();
    }

    // ---- epilogue ----
    const int rbase = row0 + warp_m * 32 + (lane >> 2);
    const int cbase = col0 + warp_n * 64 + 2 * (lane & 3);
    #pragma unroll
    for (int mt = 0; mt < 2; mt++) {
        #pragma unroll
        for (int nt = 0; nt < 8; nt++) {
            const int c = cbase + nt * 8;
            #pragma unroll
            for (int half = 0; half < 2; half++) {     // acc pairs {0,1} and {2,3}
                const int r = rbase + mt * 16 + half * 8;
                const float2 v = make_float2(acc[mt][nt][2 * half], acc[mt][nt][2 * half + 1]);
                if (MODE == 0) {
                    const int b  = r >> 12;
                    const int m  = r & 4095;
                    const int cc = c >> 10;
                    const int h  = (c & 1023) >> 6;
                    const int d  = c & 63;
                    *(float2*)&g_qkv[((((size_t)cc * Bc + b) * Hc + h) * Mc + m) * HDc + d] = v;
                } else {
                    *(float2*)&Cout[(size_t)r * HIDc + c] = v;
                }
            }
        }
    }
}

// ===========================================================================
// Attention (unchanged from passing round-2 kernel)
// ===========================================================================
#define LDP  65
#define LDPV 66
#define SMEM_ATTN ((2 * 128 * LDP + 128 * LDPV + 8 * 128) * (int)sizeof(float))

__global__ __launch_bounds__(256) void attn_kernel(const int* __restrict__ hmap) {
    const int seg = blockIdx.x;
    const int h   = blockIdx.y;
    const int b   = blockIdx.z;

    extern __shared__ float sm[];
    float* Qs = sm;
    float* Ks = Qs + 128 * LDP;
    float* Vs = Ks + 128 * LDP;
    float* Ps = Vs + 128 * LDPV;
    __shared__ int toks[128];

    const int tid = threadIdx.x;
    if (tid < 128) toks[tid] = hmap[seg * 128 + tid];
    __syncthreads();

    const size_t base_q = (((size_t)0 * Bc + b) * Hc + h) * (size_t)Mc * HDc;
    const size_t base_k = (((size_t)1 * Bc + b) * Hc + h) * (size_t)Mc * HDc;
    const size_t base_v = (((size_t)2 * Bc + b) * Hc + h) * (size_t)Mc * HDc;

    for (int i = tid; i < 128 * 64; i += 256) {
        const int row = i >> 6;
        const int d   = i & 63;
        const size_t off = (size_t)toks[row] * HDc + d;
        Qs[row * LDP  + d] = g_qkv[base_q + off];
        Ks[row * LDP  + d] = g_qkv[base_k + off];
        Vs[row * LDPV + d] = g_qkv[base_v + off];
    }
    __syncthreads();

    const int warp = tid >> 5;
    const int lane = tid & 31;

    for (int r = 0; r < 16; r++) {
        const int s = warp * 16 + r;
        const bool row_active = ((s & 1) == 0);

        float sc[4] = {0.f, 0.f, 0.f, 0.f};
#pragma unroll 8
        for (int d = 0; d < 64; d++) {
            const float qd = Qs[s * LDP + d];
#pragma unroll
            for (int j = 0; j < 4; j++)
                sc[j] += qd * Ks[(lane + 32 * j) * LDP + d];
        }

        float mx = -1e30f;
#pragma unroll
        for (int j = 0; j < 4; j++) {
            const int t = lane + 32 * j;
            const bool ok = row_active || ((t & 1) == 0);
            sc[j] = ok ? sc[j] * SCALEc : -1e30f;
            mx = fmaxf(mx, sc[j]);
        }
#pragma unroll
        for (int o = 16; o > 0; o >>= 1)
            mx = fmaxf(mx, __shfl_xor_sync(0xffffffffu, mx, o));

        float sum = 0.f;
#pragma unroll
        for (int j = 0; j < 4; j++) { sc[j] = __expf(sc[j] - mx); sum += sc[j]; }
#pragma unroll
        for (int o = 16; o > 0; o >>= 1)
            sum += __shfl_xor_sync(0xffffffffu, sum, o);
        const float inv = 1.0f / sum;

#pragma unroll
        for (int j = 0; j < 4; j++)
            Ps[warp * 128 + lane + 32 * j] = sc[j] * inv;
        __syncwarp();

        float o0 = 0.f, o1 = 0.f;
#pragma unroll 4
        for (int t = 0; t < 128; t++) {
            const float p = Ps[warp * 128 + t];
            const float2 v2 = *(const float2*)&Vs[t * LDPV + 2 * lane];
            o0 += p * v2.x;
            o1 += p * v2.y;
        }

        const size_t orow = ((size_t)b * Mc + (size_t)seg * 128 + s) * HIDc + h * 64;
        g_attn[orow + 2 * lane]     = o0;
        g_attn[orow + 2 * lane + 1] = o1;
        __syncwarp();
    }
}

// ===========================================================================
extern "C" void kernel_launch(void* const* d_in, const int* in_sizes, int n_in,
                              void* d_out, int out_size) {
    const float* x     = (const float*)d_in[0];
    const float* w_qkv = (const float*)d_in[1];
    const float* w_out = (const float*)d_in[2];
    const int*   hmap  = (const int*)d_in[3];
    float*       out   = (float*)d_out;

    cudaFuncSetAttribute(attn_kernel, cudaFuncAttributeMaxDynamicSharedMemorySize, SMEM_ATTN);

    // QKV projection: 16384 x 3072 x 1024 (bf16x3 tensor cores)
    {
        dim3 grid(3072 / 128, (Bc * Mc) / 128);   // (24, 128)
        tgemm_kernel<0><<<grid, 256>>>(x, w_qkv, nullptr);
    }
    // Hilbert-gathered segmented attention
    {
        dim3 grid(NSEGc, Hc, Bc);                 // (32, 16, 4)
        attn_kernel<<<grid, 256, SMEM_ATTN>>>(hmap);
    }
    // Output projection: 16384 x 1024 x 1024 (bf16x3 tensor cores)
    {
        dim3 grid(HIDc / 128, (Bc * Mc) / 128);   // (8, 128)
        tgemm_kernel<1><<<grid, 256>>>(nullptr, w_out, out);
    }
}

// round 5
// speedup vs baseline: 2.2727x; 1.0081x over previous
#include <cuda_runtime.h>
#include <cuda_bf16.h>
#include <cstdint>

// Problem constants
#define Bc    4
#define Mc    4096
#define HIDc  1024
#define Hc    16
#define HDc   64
#define NSEGc 32
#define SCALEc 0.125f

// ---------------------------------------------------------------------------
// Static device scratch (allocation-free per harness rules)
// ---------------------------------------------------------------------------
__device__ float g_qkv[(size_t)3 * Bc * Hc * Mc * HDc];           // [c][b][h][m][d] fp32
__device__ __nv_bfloat16 g_xhi[(size_t)Bc * Mc * HIDc];           // pre-split x
__device__ __nv_bfloat16 g_xlo[(size_t)Bc * Mc * HIDc];
__device__ __nv_bfloat16 g_wqkv_hi[(size_t)3 * HIDc * HIDc];
__device__ __nv_bfloat16 g_wqkv_lo[(size_t)3 * HIDc * HIDc];
__device__ __nv_bfloat16 g_wout_hi[(size_t)HIDc * HIDc];
__device__ __nv_bfloat16 g_wout_lo[(size_t)HIDc * HIDc];
__device__ __nv_bfloat16 g_attn_hi[(size_t)Bc * Mc * HIDc];       // attention out, split
__device__ __nv_bfloat16 g_attn_lo[(size_t)Bc * Mc * HIDc];

// ===========================================================================
// Helpers
// ===========================================================================
__device__ __forceinline__ uint32_t smem_u32(const void* p) {
    uint32_t a;
    asm("{ .reg .u64 t; cvta.to.shared.u64 t, %1; cvt.u32.u64 %0, t; }"
        : "=r"(a) : "l"(p));
    return a;
}

__device__ __forceinline__ void ldsm_x4(uint32_t* r, uint32_t addr) {
    asm volatile("ldmatrix.sync.aligned.m8n8.x4.shared.b16 {%0,%1,%2,%3}, [%4];"
                 : "=r"(r[0]), "=r"(r[1]), "=r"(r[2]), "=r"(r[3]) : "r"(addr));
}

__device__ __forceinline__ void mma_bf16(float* c, const uint32_t* a,
                                         uint32_t b0, uint32_t b1) {
    asm volatile(
        "mma.sync.aligned.m16n8k16.row.col.f32.bf16.bf16.f32 "
        "{%0,%1,%2,%3}, {%4,%5,%6,%7}, {%8,%9}, {%0,%1,%2,%3};"
        : "+f"(c[0]), "+f"(c[1]), "+f"(c[2]), "+f"(c[3])
        : "r"(a[0]), "r"(a[1]), "r"(a[2]), "r"(a[3]), "r"(b0), "r"(b1));
}

// ===========================================================================
// Pre-split kernel: fp32 -> (bf16 hi, bf16 lo), 4 elems/thread
// ===========================================================================
__global__ __launch_bounds__(256) void split_kernel(const float* __restrict__ src,
                                                    __nv_bfloat16* __restrict__ hi,
                                                    __nv_bfloat16* __restrict__ lo,
                                                    int n4) {
    const int i = blockIdx.x * 256 + threadIdx.x;
    if (i >= n4) return;
    const float4 v = ((const float4*)src)[i];
    __nv_bfloat16 h[4], l[4];
    const float* f = &v.x;
#pragma unroll
    for (int j = 0; j < 4; j++) {
        h[j] = __float2bfloat16_rn(f[j]);
        l[j] = __float2bfloat16_rn(f[j] - __bfloat162float(h[j]));
    }
    ((__nv_bfloat162*)hi)[2 * i]     = __halves2bfloat162(h[0], h[1]);
    ((__nv_bfloat162*)hi)[2 * i + 1] = __halves2bfloat162(h[2], h[3]);
    ((__nv_bfloat162*)lo)[2 * i]     = __halves2bfloat162(l[0], l[1]);
    ((__nv_bfloat162*)lo)[2 * i + 1] = __halves2bfloat162(l[2], l[3]);
}

// ===========================================================================
// bf16x3 tensor GEMM on PRE-SPLIT operands.
// C[row][col] = sum_k A[row][k] * W[col][k]
// 128x128 tile, K-chunk 32, 256 threads, warp grid 4(m) x 2(n), warp tile 32x64.
// Double-buffered SMEM (2 stages x 4 tiles x [128][40] bf16), 1 sync/iter.
// MODE 0: epilogue scatters into g_qkv;  MODE 1: row-major out.
// ===========================================================================
#define TK        32
#define NITER     (HIDc / TK)             // 32
#define LDSTR     40                       // bf16 elems per SMEM row (80 B)
#define TILE_HB   (128 * LDSTR * 2)        // 10240 B per tile
#define STAGE_B   (4 * TILE_HB)            // 40960 B per stage
#define GEMM_SMEM (2 * STAGE_B)            // 81920 B

template <int MODE>
__global__ __launch_bounds__(256, 2) void tgemm_kernel(
        const __nv_bfloat16* __restrict__ Ahi_g, const __nv_bfloat16* __restrict__ Alo_g,
        const __nv_bfloat16* __restrict__ Bhi_g, const __nv_bfloat16* __restrict__ Blo_g,
        float* __restrict__ Cout) {
    extern __shared__ __align__(16) char smraw[];
    const uint32_t smb = smem_u32(smraw);

    const int tid  = threadIdx.x;
    const int wid  = tid >> 5;
    const int lane = tid & 31;
    const int row0 = blockIdx.y * 128;
    const int col0 = blockIdx.x * 128;
    const int warp_m = wid & 3;
    const int warp_n = wid >> 2;

    // ---- global load mapping: 2 uint4 chunks per buffer per thread ----
    const __nv_bfloat16* pa_h[2]; const __nv_bfloat16* pa_l[2];
    const __nv_bfloat16* pb_h[2]; const __nv_bfloat16* pb_l[2];
    uint32_t sto[2];
#pragma unroll
    for (int t = 0; t < 2; t++) {
        const int ci  = tid + 256 * t;
        const int row = ci >> 2;           // 0..127
        const int c16 = ci & 3;            // 16B chunk (8 bf16) within 32-elem row
        pa_h[t] = Ahi_g + (size_t)(row0 + row) * HIDc + c16 * 8;
        pa_l[t] = Alo_g + (size_t)(row0 + row) * HIDc + c16 * 8;
        pb_h[t] = Bhi_g + (size_t)(col0 + row) * HIDc + c16 * 8;
        pb_l[t] = Blo_g + (size_t)(col0 + row) * HIDc + c16 * 8;
        sto[t]  = (uint32_t)(row * (LDSTR * 2) + c16 * 16);
    }

    // ---- ldmatrix bases (within a stage; add stage offset + tile offset) ----
    const int sub = lane >> 3;
    const int r8  = lane & 7;
    uint32_t a_lm[2], b_lm[4];
#pragma unroll
    for (int mt = 0; mt < 2; mt++) {
        const int row = warp_m * 32 + mt * 16 + (sub & 1) * 8 + r8;
        a_lm[mt] = smb + row * (LDSTR * 2) + (sub >> 1) * 16;
    }
#pragma unroll
    for (int np = 0; np < 4; np++) {
        const int row = warp_n * 64 + np * 16 + (sub >> 1) * 8 + r8;
        b_lm[np] = smb + row * (LDSTR * 2) + (sub & 1) * 16;
    }

    float acc[2][8][4];
#pragma unroll
    for (int i = 0; i < 2; i++)
#pragma unroll
        for (int j = 0; j < 8; j++)
#pragma unroll
            for (int q = 0; q < 4; q++) acc[i][j][q] = 0.0f;

    // ---- prologue: chunk 0 -> stage 0 ----
    uint4 rah[2], ral[2], rbh[2], rbl[2];
#pragma unroll
    for (int t = 0; t < 2; t++) {
        rah[t] = *(const uint4*)(pa_h[t]);  ral[t] = *(const uint4*)(pa_l[t]);
        rbh[t] = *(const uint4*)(pb_h[t]);  rbl[t] = *(const uint4*)(pb_l[t]);
    }
#pragma unroll
    for (int t = 0; t < 2; t++) {
        *(uint4*)(smraw + 0 * TILE_HB + sto[t]) = rah[t];
        *(uint4*)(smraw + 1 * TILE_HB + sto[t]) = ral[t];
        *(uint4*)(smraw + 2 * TILE_HB + sto[t]) = rbh[t];
        *(uint4*)(smraw + 3 * TILE_HB + sto[t]) = rbl[t];
    }
    __syncthreads();

    for (int it = 0; it < NITER; it++) {
        const uint32_t stg = (uint32_t)(it & 1) * STAGE_B;

        // prefetch next K-chunk while MMAs run
        if (it + 1 < NITER) {
            const int k0 = (it + 1) * TK;
#pragma unroll
            for (int t = 0; t < 2; t++) {
                rah[t] = *(const uint4*)(pa_h[t] + k0);
                ral[t] = *(const uint4*)(pa_l[t] + k0);
                rbh[t] = *(const uint4*)(pb_h[t] + k0);
                rbl[t] = *(const uint4*)(pb_l[t] + k0);
            }
        }

        // ---- MMA phase on stage (it&1): 3 sweeps of 16 independent MMAs ----
#pragma unroll
        for (int k16 = 0; k16 < 2; k16++) {
            const uint32_t kb = stg + k16 * 32;
            uint32_t Ah[2][4], Al[2][4], Bf[4][4];
#pragma unroll
            for (int mt = 0; mt < 2; mt++) {
                ldsm_x4(Ah[mt], a_lm[mt] + kb);                       // AHI
                ldsm_x4(Al[mt], a_lm[mt] + kb + 1 * TILE_HB);         // ALO
            }
#pragma unroll
            for (int np = 0; np < 4; np++)
                ldsm_x4(Bf[np], b_lm[np] + kb + 2 * TILE_HB);         // BHI
            // sweep 1: Ah*Bh (16 independent)
#pragma unroll
            for (int mt = 0; mt < 2; mt++)
#pragma unroll
                for (int np = 0; np < 4; np++) {
                    mma_bf16(acc[mt][2 * np],     Ah[mt], Bf[np][0], Bf[np][1]);
                    mma_bf16(acc[mt][2 * np + 1], Ah[mt], Bf[np][2], Bf[np][3]);
                }
            // sweep 2: Al*Bh
#pragma unroll
            for (int mt = 0; mt < 2; mt++)
#pragma unroll
                for (int np = 0; np < 4; np++) {
                    mma_bf16(acc[mt][2 * np],     Al[mt], Bf[np][0], Bf[np][1]);
                    mma_bf16(acc[mt][2 * np + 1], Al[mt], Bf[np][2], Bf[np][3]);
                }
            // sweep 3: Ah*Bl
#pragma unroll
            for (int np = 0; np < 4; np++)
                ldsm_x4(Bf[np], b_lm[np] + kb + 3 * TILE_HB);         // BLO
#pragma unroll
            for (int mt = 0; mt < 2; mt++)
#pragma unroll
                for (int np = 0; np < 4; np++) {
                    mma_bf16(acc[mt][2 * np],     Ah[mt], Bf[np][0], Bf[np][1]);
                    mma_bf16(acc[mt][2 * np + 1], Ah[mt], Bf[np][2], Bf[np][3]);
                }
        }

        // ---- STS prefetched chunk into the other stage ----
        if (it + 1 < NITER) {
            char* dst = smraw + (((it + 1) & 1) ? STAGE_B : 0);
#pragma unroll
            for (int t = 0; t < 2; t++) {
                *(uint4*)(dst + 0 * TILE_HB + sto[t]) = rah[t];
                *(uint4*)(dst + 1 * TILE_HB + sto[t]) = ral[t];
                *(uint4*)(dst + 2 * TILE_HB + sto[t]) = rbh[t];
                *(uint4*)(dst + 3 * TILE_HB + sto[t]) = rbl[t];
            }
        }
        __syncthreads();
    }

    // ---- epilogue ----
    const int rbase = row0 + warp_m * 32 + (lane >> 2);
    const int cbase = col0 + warp_n * 64 + 2 * (lane & 3);
#pragma unroll
    for (int mt = 0; mt < 2; mt++) {
#pragma unroll
        for (int nt = 0; nt < 8; nt++) {
            const int c = cbase + nt * 8;
#pragma unroll
            for (int half = 0; half < 2; half++) {
                const int r = rbase + mt * 16 + half * 8;
                const float2 v = make_float2(acc[mt][nt][2 * half], acc[mt][nt][2 * half + 1]);
                if (MODE == 0) {
                    const int b  = r >> 12;
                    const int m  = r & 4095;
                    const int cc = c >> 10;
                    const int h  = (c & 1023) >> 6;
                    const int d  = c & 63;
                    *(float2*)&g_qkv[((((size_t)cc * Bc + b) * Hc + h) * Mc + m) * HDc + d] = v;
                } else {
                    *(float2*)&Cout[(size_t)r * HIDc + c] = v;
                }
            }
        }
    }
}

// ===========================================================================
// Attention: unchanged math; output written PRE-SPLIT (bf16 hi/lo) so the
// out-projection GEMM consumes it directly.
// ===========================================================================
#define LDP  65
#define LDPV 66
#define SMEM_ATTN ((2 * 128 * LDP + 128 * LDPV + 8 * 128) * (int)sizeof(float))

__global__ __launch_bounds__(256) void attn_kernel(const int* __restrict__ hmap) {
    const int seg = blockIdx.x;
    const int h   = blockIdx.y;
    const int b   = blockIdx.z;

    extern __shared__ float sm[];
    float* Qs = sm;
    float* Ks = Qs + 128 * LDP;
    float* Vs = Ks + 128 * LDP;
    float* Ps = Vs + 128 * LDPV;
    __shared__ int toks[128];

    const int tid = threadIdx.x;
    if (tid < 128) toks[tid] = hmap[seg * 128 + tid];
    __syncthreads();

    const size_t base_q = (((size_t)0 * Bc + b) * Hc + h) * (size_t)Mc * HDc;
    const size_t base_k = (((size_t)1 * Bc + b) * Hc + h) * (size_t)Mc * HDc;
    const size_t base_v = (((size_t)2 * Bc + b) * Hc + h) * (size_t)Mc * HDc;

    for (int i = tid; i < 128 * 64; i += 256) {
        const int row = i >> 6;
        const int d   = i & 63;
        const size_t off = (size_t)toks[row] * HDc + d;
        Qs[row * LDP  + d] = g_qkv[base_q + off];
        Ks[row * LDP  + d] = g_qkv[base_k + off];
        Vs[row * LDPV + d] = g_qkv[base_v + off];
    }
    __syncthreads();

    const int warp = tid >> 5;
    const int lane = tid & 31;

    for (int r = 0; r < 16; r++) {
        const int s = warp * 16 + r;
        const bool row_active = ((s & 1) == 0);

        float sc[4] = {0.f, 0.f, 0.f, 0.f};
#pragma unroll 8
        for (int d = 0; d < 64; d++) {
            const float qd = Qs[s * LDP + d];
#pragma unroll
            for (int j = 0; j < 4; j++)
                sc[j] += qd * Ks[(lane + 32 * j) * LDP + d];
        }

        float mx = -1e30f;
#pragma unroll
        for (int j = 0; j < 4; j++) {
            const int t = lane + 32 * j;
            const bool ok = row_active || ((t & 1) == 0);
            sc[j] = ok ? sc[j] * SCALEc : -1e30f;
            mx = fmaxf(mx, sc[j]);
        }
#pragma unroll
        for (int o = 16; o > 0; o >>= 1)
            mx = fmaxf(mx, __shfl_xor_sync(0xffffffffu, mx, o));

        float sum = 0.f;
#pragma unroll
        for (int j = 0; j < 4; j++) { sc[j] = __expf(sc[j] - mx); sum += sc[j]; }
#pragma unroll
        for (int o = 16; o > 0; o >>= 1)
            sum += __shfl_xor_sync(0xffffffffu, sum, o);
        const float inv = 1.0f / sum;

#pragma unroll
        for (int j = 0; j < 4; j++)
            Ps[warp * 128 + lane + 32 * j] = sc[j] * inv;
        __syncwarp();

        float o0 = 0.f, o1 = 0.f;
#pragma unroll 4
        for (int t = 0; t < 128; t++) {
            const float p = Ps[warp * 128 + t];
            const float2 v2 = *(const float2*)&Vs[t * LDPV + 2 * lane];
            o0 += p * v2.x;
            o1 += p * v2.y;
        }

        // write split bf16 hi/lo directly
        const size_t orow = ((size_t)b * Mc + (size_t)seg * 128 + s) * HIDc + h * 64 + 2 * lane;
        __nv_bfloat16 h0 = __float2bfloat16_rn(o0);
        __nv_bfloat16 h1 = __float2bfloat16_rn(o1);
        __nv_bfloat16 l0 = __float2bfloat16_rn(o0 - __bfloat162float(h0));
        __nv_bfloat16 l1 = __float2bfloat16_rn(o1 - __bfloat162float(h1));
        *(__nv_bfloat162*)&g_attn_hi[orow] = __halves2bfloat162(h0, h1);
        *(__nv_bfloat162*)&g_attn_lo[orow] = __halves2bfloat162(l0, l1);
        __syncwarp();
    }
}

// ===========================================================================
extern "C" void kernel_launch(void* const* d_in, const int* in_sizes, int n_in,
                              void* d_out, int out_size) {
    const float* x     = (const float*)d_in[0];
    const float* w_qkv = (const float*)d_in[1];
    const float* w_out = (const float*)d_in[2];
    const int*   hmap  = (const int*)d_in[3];
    float*       out   = (float*)d_out;

    cudaFuncSetAttribute(tgemm_kernel<0>, cudaFuncAttributeMaxDynamicSharedMemorySize, GEMM_SMEM);
    cudaFuncSetAttribute(tgemm_kernel<1>, cudaFuncAttributeMaxDynamicSharedMemorySize, GEMM_SMEM);
    cudaFuncSetAttribute(attn_kernel,     cudaFuncAttributeMaxDynamicSharedMemorySize, SMEM_ATTN);

    __nv_bfloat16 *xhi, *xlo, *wqh, *wql, *woh, *wol, *ahi, *alo;
    cudaGetSymbolAddress((void**)&xhi, g_xhi);
    cudaGetSymbolAddress((void**)&xlo, g_xlo);
    cudaGetSymbolAddress((void**)&wqh, g_wqkv_hi);
    cudaGetSymbolAddress((void**)&wql, g_wqkv_lo);
    cudaGetSymbolAddress((void**)&woh, g_wout_hi);
    cudaGetSymbolAddress((void**)&wol, g_wout_lo);
    cudaGetSymbolAddress((void**)&ahi, g_attn_hi);
    cudaGetSymbolAddress((void**)&alo, g_attn_lo);

    // Pre-split x, w_qkv, w_out into bf16 hi/lo
    {
        int n4 = (Bc * Mc * HIDc) / 4;
        split_kernel<<<(n4 + 255) / 256, 256>>>(x, xhi, xlo, n4);
        n4 = (3 * HIDc * HIDc) / 4;
        split_kernel<<<(n4 + 255) / 256, 256>>>(w_qkv, wqh, wql, n4);
        n4 = (HIDc * HIDc) / 4;
        split_kernel<<<(n4 + 255) / 256, 256>>>(w_out, woh, wol, n4);
    }
    // QKV projection: 16384 x 3072 x 1024
    {
        dim3 grid(3072 / 128, (Bc * Mc) / 128);   // (24, 128)
        tgemm_kernel<0><<<grid, 256, GEMM_SMEM>>>(xhi, xlo, wqh, wql, nullptr);
    }
    // Hilbert-gathered segmented attention
    {
        dim3 grid(NSEGc, Hc, Bc);                 // (32, 16, 4)
        attn_kernel<<<grid, 256, SMEM_ATTN>>>(hmap);
    }
    // Output projection: 16384 x 1024 x 1024
    {
        dim3 grid(HIDc / 128, (Bc * Mc) / 128);   // (8, 128)
        tgemm_kernel<1><<<grid, 256, GEMM_SMEM>>>(ahi, alo, woh, wol, out);
    }
}

// round 6
// speedup vs baseline: 2.6797x; 1.1791x over previous
#include <cuda_runtime.h>
#include <cuda_bf16.h>
#include <cstdint>

// Problem constants
#define Bc    4
#define Mc    4096
#define HIDc  1024
#define Hc    16
#define HDc   64
#define NSEGc 32
#define SCALEc 0.125f

// ---------------------------------------------------------------------------
// Static device scratch (allocation-free per harness rules)
// ---------------------------------------------------------------------------
__device__ float g_qkv[(size_t)3 * Bc * Hc * Mc * HDc];           // [c][b][h][m][d] fp32
__device__ __nv_bfloat16 g_xhi[(size_t)Bc * Mc * HIDc];
__device__ __nv_bfloat16 g_xlo[(size_t)Bc * Mc * HIDc];
__device__ __nv_bfloat16 g_wqkv_hi[(size_t)3 * HIDc * HIDc];
__device__ __nv_bfloat16 g_wqkv_lo[(size_t)3 * HIDc * HIDc];
__device__ __nv_bfloat16 g_wout_hi[(size_t)HIDc * HIDc];
__device__ __nv_bfloat16 g_wout_lo[(size_t)HIDc * HIDc];
__device__ __nv_bfloat16 g_attn_hi[(size_t)Bc * Mc * HIDc];
__device__ __nv_bfloat16 g_attn_lo[(size_t)Bc * Mc * HIDc];

// ===========================================================================
// Helpers
// ===========================================================================
__device__ __forceinline__ uint32_t smem_u32(const void* p) {
    uint32_t a;
    asm("{ .reg .u64 t; cvta.to.shared.u64 t, %1; cvt.u32.u64 %0, t; }"
        : "=r"(a) : "l"(p));
    return a;
}

__device__ __forceinline__ void ldsm_x4(uint32_t* r, uint32_t addr) {
    asm volatile("ldmatrix.sync.aligned.m8n8.x4.shared.b16 {%0,%1,%2,%3}, [%4];"
                 : "=r"(r[0]), "=r"(r[1]), "=r"(r[2]), "=r"(r[3]) : "r"(addr));
}

__device__ __forceinline__ void mma_bf16(float* c, const uint32_t* a,
                                         uint32_t b0, uint32_t b1) {
    asm volatile(
        "mma.sync.aligned.m16n8k16.row.col.f32.bf16.bf16.f32 "
        "{%0,%1,%2,%3}, {%4,%5,%6,%7}, {%8,%9}, {%0,%1,%2,%3};"
        : "+f"(c[0]), "+f"(c[1]), "+f"(c[2]), "+f"(c[3])
        : "r"(a[0]), "r"(a[1]), "r"(a[2]), "r"(a[3]), "r"(b0), "r"(b1));
}

__device__ __forceinline__ void cp_async16(uint32_t dst, const void* src) {
    asm volatile("cp.async.cg.shared.global [%0], [%1], 16;"
                 :: "r"(dst), "l"(src) : "memory");
}
#define CP_COMMIT() asm volatile("cp.async.commit_group;" ::: "memory")
#define CP_WAIT0()  asm volatile("cp.async.wait_group 0;" ::: "memory")

// ===========================================================================
// Pre-split kernel: fp32 -> (bf16 hi, bf16 lo), 4 elems/thread
// ===========================================================================
__global__ __launch_bounds__(256) void split_kernel(const float* __restrict__ src,
                                                    __nv_bfloat16* __restrict__ hi,
                                                    __nv_bfloat16* __restrict__ lo,
                                                    int n4) {
    const int i = blockIdx.x * 256 + threadIdx.x;
    if (i >= n4) return;
    const float4 v = ((const float4*)src)[i];
    __nv_bfloat16 h[4], l[4];
    const float* f = &v.x;
#pragma unroll
    for (int j = 0; j < 4; j++) {
        h[j] = __float2bfloat16_rn(f[j]);
        l[j] = __float2bfloat16_rn(f[j] - __bfloat162float(h[j]));
    }
    ((__nv_bfloat162*)hi)[2 * i]     = __halves2bfloat162(h[0], h[1]);
    ((__nv_bfloat162*)hi)[2 * i + 1] = __halves2bfloat162(h[2], h[3]);
    ((__nv_bfloat162*)lo)[2 * i]     = __halves2bfloat162(l[0], l[1]);
    ((__nv_bfloat162*)lo)[2 * i + 1] = __halves2bfloat162(l[2], l[3]);
}

// ===========================================================================
// bf16x3 tensor GEMM, cp.async double-buffered.
// C[row][col] = sum_k A[row][k] * W[col][k]
// 128x128 tile, K-chunk 32, 256 threads, warp grid 4(m) x 2(n).
// ===========================================================================
#define TK        32
#define NITER     (HIDc / TK)              // 32
#define LDSTR     40                        // bf16 elems per SMEM row (80 B)
#define TILE_HB   (128 * LDSTR * 2)         // 10240 B per tile
#define STAGE_B   (4 * TILE_HB)             // 40960 B per stage
#define GEMM_SMEM (2 * STAGE_B)             // 81920 B

template <int MODE>
__global__ __launch_bounds__(256, 2) void tgemm_kernel(
        const __nv_bfloat16* __restrict__ Ahi_g, const __nv_bfloat16* __restrict__ Alo_g,
        const __nv_bfloat16* __restrict__ Bhi_g, const __nv_bfloat16* __restrict__ Blo_g,
        float* __restrict__ Cout) {
    extern __shared__ __align__(16) char smraw[];
    const uint32_t smb = smem_u32(smraw);

    const int tid  = threadIdx.x;
    const int wid  = tid >> 5;
    const int lane = tid & 31;
    const int row0 = blockIdx.y * 128;
    const int col0 = blockIdx.x * 128;
    const int warp_m = wid & 3;
    const int warp_n = wid >> 2;

    // ---- cp.async stream setup: 8 streams (4 tiles x 2 chunks) per thread ----
    const __nv_bfloat16* src[8];
    uint32_t rel[8];
#pragma unroll
    for (int t = 0; t < 2; t++) {
        const int ci  = tid + 256 * t;
        const int row = ci >> 2;            // 0..127
        const int c16 = ci & 3;             // 16B chunk within 32-elem K-row
        const size_t offA = (size_t)(row0 + row) * HIDc + c16 * 8;
        const size_t offB = (size_t)(col0 + row) * HIDc + c16 * 8;
        const uint32_t so = (uint32_t)(row * (LDSTR * 2) + c16 * 16);
        src[4 * t + 0] = Ahi_g + offA;  rel[4 * t + 0] = 0 * TILE_HB + so;
        src[4 * t + 1] = Alo_g + offA;  rel[4 * t + 1] = 1 * TILE_HB + so;
        src[4 * t + 2] = Bhi_g + offB;  rel[4 * t + 2] = 2 * TILE_HB + so;
        src[4 * t + 3] = Blo_g + offB;  rel[4 * t + 3] = 3 * TILE_HB + so;
    }

    // ---- ldmatrix bases ----
    const int sub = lane >> 3;
    const int r8  = lane & 7;
    uint32_t a_lm[2], b_lm[4];
#pragma unroll
    for (int mt = 0; mt < 2; mt++) {
        const int row = warp_m * 32 + mt * 16 + (sub & 1) * 8 + r8;
        a_lm[mt] = smb + row * (LDSTR * 2) + (sub >> 1) * 16;
    }
#pragma unroll
    for (int np = 0; np < 4; np++) {
        const int row = warp_n * 64 + np * 16 + (sub >> 1) * 8 + r8;
        b_lm[np] = smb + row * (LDSTR * 2) + (sub & 1) * 16;
    }

    float acc[2][8][4];
#pragma unroll
    for (int i = 0; i < 2; i++)
#pragma unroll
        for (int j = 0; j < 8; j++)
#pragma unroll
            for (int q = 0; q < 4; q++) acc[i][j][q] = 0.0f;

    // ---- prologue: stage 0 ----
#pragma unroll
    for (int j = 0; j < 8; j++) cp_async16(smb + rel[j], src[j]);
    CP_COMMIT();

    for (int it = 0; it < NITER; it++) {
        CP_WAIT0();
        __syncthreads();
        const uint32_t stg = (uint32_t)(it & 1) * STAGE_B;

        // issue next stage (lands during MMA phase)
        if (it + 1 < NITER) {
            const uint32_t nst = smb + (uint32_t)((it + 1) & 1) * STAGE_B;
#pragma unroll
            for (int j = 0; j < 8; j++) {
                src[j] += TK;
                cp_async16(nst + rel[j], src[j]);
            }
            CP_COMMIT();
        }

        // ---- MMA phase: 3 sweeps of 16 independent MMAs per k16 ----
#pragma unroll
        for (int k16 = 0; k16 < 2; k16++) {
            const uint32_t kb = stg + k16 * 32;
            uint32_t Ah[2][4], Al[2][4], Bf[4][4];
#pragma unroll
            for (int mt = 0; mt < 2; mt++) {
                ldsm_x4(Ah[mt], a_lm[mt] + kb);                   // AHI
                ldsm_x4(Al[mt], a_lm[mt] + kb + 1 * TILE_HB);     // ALO
            }
#pragma unroll
            for (int np = 0; np < 4; np++)
                ldsm_x4(Bf[np], b_lm[np] + kb + 2 * TILE_HB);     // BHI
#pragma unroll
            for (int mt = 0; mt < 2; mt++)
#pragma unroll
                for (int np = 0; np < 4; np++) {
                    mma_bf16(acc[mt][2 * np],     Ah[mt], Bf[np][0], Bf[np][1]);
                    mma_bf16(acc[mt][2 * np + 1], Ah[mt], Bf[np][2], Bf[np][3]);
                }
#pragma unroll
            for (int mt = 0; mt < 2; mt++)
#pragma unroll
                for (int np = 0; np < 4; np++) {
                    mma_bf16(acc[mt][2 * np],     Al[mt], Bf[np][0], Bf[np][1]);
                    mma_bf16(acc[mt][2 * np + 1], Al[mt], Bf[np][2], Bf[np][3]);
                }
#pragma unroll
            for (int np = 0; np < 4; np++)
                ldsm_x4(Bf[np], b_lm[np] + kb + 3 * TILE_HB);     // BLO
#pragma unroll
            for (int mt = 0; mt < 2; mt++)
#pragma unroll
                for (int np = 0; np < 4; np++) {
                    mma_bf16(acc[mt][2 * np],     Ah[mt], Bf[np][0], Bf[np][1]);
                    mma_bf16(acc[mt][2 * np + 1], Ah[mt], Bf[np][2], Bf[np][3]);
                }
        }
        __syncthreads();
    }

    // ---- epilogue ----
    const int rbase = row0 + warp_m * 32 + (lane >> 2);
    const int cbase = col0 + warp_n * 64 + 2 * (lane & 3);
#pragma unroll
    for (int mt = 0; mt < 2; mt++) {
#pragma unroll
        for (int nt = 0; nt < 8; nt++) {
            const int c = cbase + nt * 8;
#pragma unroll
            for (int half = 0; half < 2; half++) {
                const int r = rbase + mt * 16 + half * 8;
                const float2 v = make_float2(acc[mt][nt][2 * half], acc[mt][nt][2 * half + 1]);
                if (MODE == 0) {
                    const int b  = r >> 12;
                    const int m  = r & 4095;
                    const int cc = c >> 10;
                    const int h  = (c & 1023) >> 6;
                    const int d  = c & 63;
                    *(float2*)&g_qkv[((((size_t)cc * Bc + b) * Hc + h) * Mc + m) * HDc + d] = v;
                } else {
                    *(float2*)&Cout[(size_t)r * HIDc + c] = v;
                }
            }
        }
    }
}

// ===========================================================================
// Attention: float4 gather loads + 4-row register blocking.
// Output written pre-split (bf16 hi/lo) for the out-projection GEMM.
// ===========================================================================
#define LDP  65
#define LDPV 66
#define SMEM_ATTN ((2 * 128 * LDP + 128 * LDPV + 32 * 128) * (int)sizeof(float))

__global__ __launch_bounds__(256) void attn_kernel(const int* __restrict__ hmap) {
    const int seg = blockIdx.x;
    const int h   = blockIdx.y;
    const int b   = blockIdx.z;

    extern __shared__ float sm[];
    float* Qs = sm;                    // 128 * 65
    float* Ks = Qs + 128 * LDP;        // 128 * 65
    float* Vs = Ks + 128 * LDP;        // 128 * 66
    float* Ps = Vs + 128 * LDPV;       // 32 * 128 (8 warps x 4 rows)
    __shared__ int toks[128];

    const int tid = threadIdx.x;
    if (tid < 128) toks[tid] = hmap[seg * 128 + tid];
    __syncthreads();

    const size_t base_q = (((size_t)0 * Bc + b) * Hc + h) * (size_t)Mc * HDc;
    const size_t base_k = (((size_t)1 * Bc + b) * Hc + h) * (size_t)Mc * HDc;
    const size_t base_v = (((size_t)2 * Bc + b) * Hc + h) * (size_t)Mc * HDc;

    // float4 gather: 2048 chunks of 16B per tensor, 8 per thread
    for (int i = tid; i < 2048; i += 256) {
        const int row = i >> 4;
        const int c4  = (i & 15) * 4;
        const size_t off = (size_t)toks[row] * HDc + c4;
        const float4 q4 = *(const float4*)&g_qkv[base_q + off];
        const float4 k4 = *(const float4*)&g_qkv[base_k + off];
        const float4 v4 = *(const float4*)&g_qkv[base_v + off];
        float* qd = &Qs[row * LDP  + c4];
        float* kd = &Ks[row * LDP  + c4];
        float* vd = &Vs[row * LDPV + c4];
        qd[0] = q4.x; qd[1] = q4.y; qd[2] = q4.z; qd[3] = q4.w;
        kd[0] = k4.x; kd[1] = k4.y; kd[2] = k4.z; kd[3] = k4.w;
        vd[0] = v4.x; vd[1] = v4.y; vd[2] = v4.z; vd[3] = v4.w;
    }
    __syncthreads();

    const int warp = tid >> 5;
    const int lane = tid & 31;

    for (int rb = 0; rb < 4; rb++) {
        const int s0 = warp * 16 + rb * 4;

        // ---- scores for 4 rows at once (K reads amortized) ----
        float sc[4][4];
#pragma unroll
        for (int r = 0; r < 4; r++)
#pragma unroll
            for (int j = 0; j < 4; j++) sc[r][j] = 0.0f;

#pragma unroll 4
        for (int d = 0; d < 64; d++) {
            float kv[4];
#pragma unroll
            for (int j = 0; j < 4; j++)
                kv[j] = Ks[(lane + 32 * j) * LDP + d];
#pragma unroll
            for (int r = 0; r < 4; r++) {
                const float q = Qs[(s0 + r) * LDP + d];
#pragma unroll
                for (int j = 0; j < 4; j++) sc[r][j] += q * kv[j];
            }
        }

        // ---- per-row masked softmax ----
#pragma unroll
        for (int r = 0; r < 4; r++) {
            const int s = s0 + r;
            const bool row_active = ((s & 1) == 0);   // DIL = 2
            float mx = -1e30f;
#pragma unroll
            for (int j = 0; j < 4; j++) {
                const int t = lane + 32 * j;
                const bool ok = row_active || ((t & 1) == 0);
                sc[r][j] = ok ? sc[r][j] * SCALEc : -1e30f;
                mx = fmaxf(mx, sc[r][j]);
            }
#pragma unroll
            for (int o = 16; o > 0; o >>= 1)
                mx = fmaxf(mx, __shfl_xor_sync(0xffffffffu, mx, o));
            float sum = 0.f;
#pragma unroll
            for (int j = 0; j < 4; j++) { sc[r][j] = __expf(sc[r][j] - mx); sum += sc[r][j]; }
#pragma unroll
            for (int o = 16; o > 0; o >>= 1)
                sum += __shfl_xor_sync(0xffffffffu, sum, o);
            const float inv = 1.0f / sum;
#pragma unroll
            for (int j = 0; j < 4; j++)
                Ps[(warp * 4 + r) * 128 + lane + 32 * j] = sc[r][j] * inv;
        }
        __syncwarp();

        // ---- PV for 4 rows at once (V reads amortized) ----
        float o2[4][2];
#pragma unroll
        for (int r = 0; r < 4; r++) { o2[r][0] = 0.f; o2[r][1] = 0.f; }
#pragma unroll 4
        for (int t = 0; t < 128; t++) {
            const float2 v2 = *(const float2*)&Vs[t * LDPV + 2 * lane];
#pragma unroll
            for (int r = 0; r < 4; r++) {
                const float p = Ps[(warp * 4 + r) * 128 + t];
                o2[r][0] += p * v2.x;
                o2[r][1] += p * v2.y;
            }
        }

#pragma unroll
        for (int r = 0; r < 4; r++) {
            const int s = s0 + r;
            const size_t orow = ((size_t)b * Mc + (size_t)seg * 128 + s) * HIDc + h * 64 + 2 * lane;
            __nv_bfloat16 h0 = __float2bfloat16_rn(o2[r][0]);
            __nv_bfloat16 h1 = __float2bfloat16_rn(o2[r][1]);
            __nv_bfloat16 l0 = __float2bfloat16_rn(o2[r][0] - __bfloat162float(h0));
            __nv_bfloat16 l1 = __float2bfloat16_rn(o2[r][1] - __bfloat162float(h1));
            *(__nv_bfloat162*)&g_attn_hi[orow] = __halves2bfloat162(h0, h1);
            *(__nv_bfloat162*)&g_attn_lo[orow] = __halves2bfloat162(l0, l1);
        }
        __syncwarp();
    }
}

// ===========================================================================
extern "C" void kernel_launch(void* const* d_in, const int* in_sizes, int n_in,
                              void* d_out, int out_size) {
    const float* x     = (const float*)d_in[0];
    const float* w_qkv = (const float*)d_in[1];
    const float* w_out = (const float*)d_in[2];
    const int*   hmap  = (const int*)d_in[3];
    float*       out   = (float*)d_out;

    cudaFuncSetAttribute(tgemm_kernel<0>, cudaFuncAttributeMaxDynamicSharedMemorySize, GEMM_SMEM);
    cudaFuncSetAttribute(tgemm_kernel<1>, cudaFuncAttributeMaxDynamicSharedMemorySize, GEMM_SMEM);
    cudaFuncSetAttribute(attn_kernel,     cudaFuncAttributeMaxDynamicSharedMemorySize, SMEM_ATTN);

    __nv_bfloat16 *xhi, *xlo, *wqh, *wql, *woh, *wol, *ahi, *alo;
    cudaGetSymbolAddress((void**)&xhi, g_xhi);
    cudaGetSymbolAddress((void**)&xlo, g_xlo);
    cudaGetSymbolAddress((void**)&wqh, g_wqkv_hi);
    cudaGetSymbolAddress((void**)&wql, g_wqkv_lo);
    cudaGetSymbolAddress((void**)&woh, g_wout_hi);
    cudaGetSymbolAddress((void**)&wol, g_wout_lo);
    cudaGetSymbolAddress((void**)&ahi, g_attn_hi);
    cudaGetSymbolAddress((void**)&alo, g_attn_lo);

    // Pre-split x, w_qkv, w_out into bf16 hi/lo
    {
        int n4 = (Bc * Mc * HIDc) / 4;
        split_kernel<<<(n4 + 255) / 256, 256>>>(x, xhi, xlo, n4);
        n4 = (3 * HIDc * HIDc) / 4;
        split_kernel<<<(n4 + 255) / 256, 256>>>(w_qkv, wqh, wql, n4);
        n4 = (HIDc * HIDc) / 4;
        split_kernel<<<(n4 + 255) / 256, 256>>>(w_out, woh, wol, n4);
    }
    // QKV projection: 16384 x 3072 x 1024
    {
        dim3 grid(3072 / 128, (Bc * Mc) / 128);   // (24, 128)
        tgemm_kernel<0><<<grid, 256, GEMM_SMEM>>>(xhi, xlo, wqh, wql, nullptr);
    }
    // Hilbert-gathered segmented attention
    {
        dim3 grid(NSEGc, Hc, Bc);                 // (32, 16, 4)
        attn_kernel<<<grid, 256, SMEM_ATTN>>>(hmap);
    }
    // Output projection: 16384 x 1024 x 1024
    {
        dim3 grid(HIDc / 128, (Bc * Mc) / 128);   // (8, 128)
        tgemm_kernel<1><<<grid, 256, GEMM_SMEM>>>(ahi, alo, woh, wol, out);
    }
}

// round 7
// speedup vs baseline: 3.2937x; 1.2291x over previous
#include <cuda_runtime.h>
#include <cuda_bf16.h>
#include <cstdint>

// Problem constants
#define Bc    4
#define Mc    4096
#define HIDc  1024
#define Hc    16
#define HDc   64
#define NSEGc 32
#define SCALEc 0.125f

// ---------------------------------------------------------------------------
// Static device scratch (allocation-free per harness rules)
// ---------------------------------------------------------------------------
__device__ __nv_bfloat16 g_qkv_hi[(size_t)3 * Bc * Hc * Mc * HDc];  // [c][b][h][m][d]
__device__ __nv_bfloat16 g_qkv_lo[(size_t)3 * Bc * Hc * Mc * HDc];
__device__ __nv_bfloat16 g_xhi[(size_t)Bc * Mc * HIDc];
__device__ __nv_bfloat16 g_xlo[(size_t)Bc * Mc * HIDc];
__device__ __nv_bfloat16 g_wqkv_hi[(size_t)3 * HIDc * HIDc];
__device__ __nv_bfloat16 g_wqkv_lo[(size_t)3 * HIDc * HIDc];
__device__ __nv_bfloat16 g_wout_hi[(size_t)HIDc * HIDc];
__device__ __nv_bfloat16 g_wout_lo[(size_t)HIDc * HIDc];
__device__ __nv_bfloat16 g_attn_hi[(size_t)Bc * Mc * HIDc];
__device__ __nv_bfloat16 g_attn_lo[(size_t)Bc * Mc * HIDc];

// ===========================================================================
// Helpers
// ===========================================================================
__device__ __forceinline__ uint32_t smem_u32(const void* p) {
    uint32_t a;
    asm("{ .reg .u64 t; cvta.to.shared.u64 t, %1; cvt.u32.u64 %0, t; }"
        : "=r"(a) : "l"(p));
    return a;
}

__device__ __forceinline__ void ldsm_x4(uint32_t* r, uint32_t addr) {
    asm volatile("ldmatrix.sync.aligned.m8n8.x4.shared.b16 {%0,%1,%2,%3}, [%4];"
                 : "=r"(r[0]), "=r"(r[1]), "=r"(r[2]), "=r"(r[3]) : "r"(addr));
}
__device__ __forceinline__ void ldsm_x4_t(uint32_t* r, uint32_t addr) {
    asm volatile("ldmatrix.sync.aligned.m8n8.x4.trans.shared.b16 {%0,%1,%2,%3}, [%4];"
                 : "=r"(r[0]), "=r"(r[1]), "=r"(r[2]), "=r"(r[3]) : "r"(addr));
}

__device__ __forceinline__ void mma_bf16(float* c, const uint32_t* a,
                                         uint32_t b0, uint32_t b1) {
    asm volatile(
        "mma.sync.aligned.m16n8k16.row.col.f32.bf16.bf16.f32 "
        "{%0,%1,%2,%3}, {%4,%5,%6,%7}, {%8,%9}, {%0,%1,%2,%3};"
        : "+f"(c[0]), "+f"(c[1]), "+f"(c[2]), "+f"(c[3])
        : "r"(a[0]), "r"(a[1]), "r"(a[2]), "r"(a[3]), "r"(b0), "r"(b1));
}

__device__ __forceinline__ void cp_async16(uint32_t dst, const void* src) {
    asm volatile("cp.async.cg.shared.global [%0], [%1], 16;"
                 :: "r"(dst), "l"(src) : "memory");
}
#define CP_COMMIT() asm volatile("cp.async.commit_group;" ::: "memory")
#define CP_WAIT0()  asm volatile("cp.async.wait_group 0;" ::: "memory")

__device__ __forceinline__ uint32_t pack_bf16(float x, float y) {
    __nv_bfloat162 v = __halves2bfloat162(__float2bfloat16_rn(x), __float2bfloat16_rn(y));
    return *reinterpret_cast<uint32_t*>(&v);
}

// ===========================================================================
// Pre-split kernel: fp32 -> (bf16 hi, bf16 lo)
// ===========================================================================
__global__ __launch_bounds__(256) void split_kernel(const float* __restrict__ src,
                                                    __nv_bfloat16* __restrict__ hi,
                                                    __nv_bfloat16* __restrict__ lo,
                                                    int n4) {
    const int i = blockIdx.x * 256 + threadIdx.x;
    if (i >= n4) return;
    const float4 v = ((const float4*)src)[i];
    __nv_bfloat16 h[4], l[4];
    const float* f = &v.x;
#pragma unroll
    for (int j = 0; j < 4; j++) {
        h[j] = __float2bfloat16_rn(f[j]);
        l[j] = __float2bfloat16_rn(f[j] - __bfloat162float(h[j]));
    }
    ((__nv_bfloat162*)hi)[2 * i]     = __halves2bfloat162(h[0], h[1]);
    ((__nv_bfloat162*)hi)[2 * i + 1] = __halves2bfloat162(h[2], h[3]);
    ((__nv_bfloat162*)lo)[2 * i]     = __halves2bfloat162(l[0], l[1]);
    ((__nv_bfloat162*)lo)[2 * i + 1] = __halves2bfloat162(l[2], l[3]);
}

// ===========================================================================
// bf16x3 tensor GEMM, cp.async double-buffered.
// MODE 0: epilogue splits to bf16 hi/lo and scatters into g_qkv_hi/lo.
// MODE 1: fp32 row-major out.
// ===========================================================================
#define TK        32
#define NITER     (HIDc / TK)
#define LDSTR     40
#define TILE_HB   (128 * LDSTR * 2)
#define STAGE_B   (4 * TILE_HB)
#define GEMM_SMEM (2 * STAGE_B)

template <int MODE>
__global__ __launch_bounds__(256, 2) void tgemm_kernel(
        const __nv_bfloat16* __restrict__ Ahi_g, const __nv_bfloat16* __restrict__ Alo_g,
        const __nv_bfloat16* __restrict__ Bhi_g, const __nv_bfloat16* __restrict__ Blo_g,
        float* __restrict__ Cout) {
    extern __shared__ __align__(16) char smraw[];
    const uint32_t smb = smem_u32(smraw);

    const int tid  = threadIdx.x;
    const int wid  = tid >> 5;
    const int lane = tid & 31;
    const int row0 = blockIdx.y * 128;
    const int col0 = blockIdx.x * 128;
    const int warp_m = wid & 3;
    const int warp_n = wid >> 2;

    const __nv_bfloat16* src[8];
    uint32_t rel[8];
#pragma unroll
    for (int t = 0; t < 2; t++) {
        const int ci  = tid + 256 * t;
        const int row = ci >> 2;
        const int c16 = ci & 3;
        const size_t offA = (size_t)(row0 + row) * HIDc + c16 * 8;
        const size_t offB = (size_t)(col0 + row) * HIDc + c16 * 8;
        const uint32_t so = (uint32_t)(row * (LDSTR * 2) + c16 * 16);
        src[4 * t + 0] = Ahi_g + offA;  rel[4 * t + 0] = 0 * TILE_HB + so;
        src[4 * t + 1] = Alo_g + offA;  rel[4 * t + 1] = 1 * TILE_HB + so;
        src[4 * t + 2] = Bhi_g + offB;  rel[4 * t + 2] = 2 * TILE_HB + so;
        src[4 * t + 3] = Blo_g + offB;  rel[4 * t + 3] = 3 * TILE_HB + so;
    }

    const int sub = lane >> 3;
    const int r8  = lane & 7;
    uint32_t a_lm[2], b_lm[4];
#pragma unroll
    for (int mt = 0; mt < 2; mt++) {
        const int row = warp_m * 32 + mt * 16 + (sub & 1) * 8 + r8;
        a_lm[mt] = smb + row * (LDSTR * 2) + (sub >> 1) * 16;
    }
#pragma unroll
    for (int np = 0; np < 4; np++) {
        const int row = warp_n * 64 + np * 16 + (sub >> 1) * 8 + r8;
        b_lm[np] = smb + row * (LDSTR * 2) + (sub & 1) * 16;
    }

    float acc[2][8][4];
#pragma unroll
    for (int i = 0; i < 2; i++)
#pragma unroll
        for (int j = 0; j < 8; j++)
#pragma unroll
            for (int q = 0; q < 4; q++) acc[i][j][q] = 0.0f;

#pragma unroll
    for (int j = 0; j < 8; j++) cp_async16(smb + rel[j], src[j]);
    CP_COMMIT();

    for (int it = 0; it < NITER; it++) {
        CP_WAIT0();
        __syncthreads();
        const uint32_t stg = (uint32_t)(it & 1) * STAGE_B;

        if (it + 1 < NITER) {
            const uint32_t nst = smb + (uint32_t)((it + 1) & 1) * STAGE_B;
#pragma unroll
            for (int j = 0; j < 8; j++) {
                src[j] += TK;
                cp_async16(nst + rel[j], src[j]);
            }
            CP_COMMIT();
        }

#pragma unroll
        for (int k16 = 0; k16 < 2; k16++) {
            const uint32_t kb = stg + k16 * 32;
            uint32_t Ah[2][4], Al[2][4], Bf[4][4];
#pragma unroll
            for (int mt = 0; mt < 2; mt++) {
                ldsm_x4(Ah[mt], a_lm[mt] + kb);
                ldsm_x4(Al[mt], a_lm[mt] + kb + 1 * TILE_HB);
            }
#pragma unroll
            for (int np = 0; np < 4; np++)
                ldsm_x4(Bf[np], b_lm[np] + kb + 2 * TILE_HB);
#pragma unroll
            for (int mt = 0; mt < 2; mt++)
#pragma unroll
                for (int np = 0; np < 4; np++) {
                    mma_bf16(acc[mt][2 * np],     Ah[mt], Bf[np][0], Bf[np][1]);
                    mma_bf16(acc[mt][2 * np + 1], Ah[mt], Bf[np][2], Bf[np][3]);
                }
#pragma unroll
            for (int mt = 0; mt < 2; mt++)
#pragma unroll
                for (int np = 0; np < 4; np++) {
                    mma_bf16(acc[mt][2 * np],     Al[mt], Bf[np][0], Bf[np][1]);
                    mma_bf16(acc[mt][2 * np + 1], Al[mt], Bf[np][2], Bf[np][3]);
                }
#pragma unroll
            for (int np = 0; np < 4; np++)
                ldsm_x4(Bf[np], b_lm[np] + kb + 3 * TILE_HB);
#pragma unroll
            for (int mt = 0; mt < 2; mt++)
#pragma unroll
                for (int np = 0; np < 4; np++) {
                    mma_bf16(acc[mt][2 * np],     Ah[mt], Bf[np][0], Bf[np][1]);
                    mma_bf16(acc[mt][2 * np + 1], Ah[mt], Bf[np][2], Bf[np][3]);
                }
        }
        // no trailing __syncthreads: the top-of-loop barrier orders stage reuse
    }

    // ---- epilogue ----
    const int rbase = row0 + warp_m * 32 + (lane >> 2);
    const int cbase = col0 + warp_n * 64 + 2 * (lane & 3);
#pragma unroll
    for (int mt = 0; mt < 2; mt++) {
#pragma unroll
        for (int nt = 0; nt < 8; nt++) {
            const int c = cbase + nt * 8;
#pragma unroll
            for (int half = 0; half < 2; half++) {
                const int r = rbase + mt * 16 + half * 8;
                const float vx = acc[mt][nt][2 * half];
                const float vy = acc[mt][nt][2 * half + 1];
                if (MODE == 0) {
                    const int b  = r >> 12;
                    const int m  = r & 4095;
                    const int cc = c >> 10;
                    const int h  = (c & 1023) >> 6;
                    const int d  = c & 63;
                    const size_t idx = ((((size_t)cc * Bc + b) * Hc + h) * Mc + m) * HDc + d;
                    const __nv_bfloat16 hx = __float2bfloat16_rn(vx);
                    const __nv_bfloat16 hy = __float2bfloat16_rn(vy);
                    *(uint32_t*)&g_qkv_hi[idx] = pack_bf16(vx, vy);
                    *(uint32_t*)&g_qkv_lo[idx] =
                        pack_bf16(vx - __bfloat162float(hx), vy - __bfloat162float(hy));
                } else {
                    *(float2*)&Cout[(size_t)r * HIDc + c] = make_float2(vx, vy);
                }
            }
        }
    }
}

// ===========================================================================
// Tensor-core attention: one block per (seg,h,b), 8 warps.
// S = QK^T (bf16x3), in-register masked softmax, P·V (bf16x3).
// SMEM: Q/K/V hi+lo bf16 [128][72]; P hi/lo [128][136] overlaid on Q/K.
// ===========================================================================
#define ATT_SMEM 110592   // 6 * 18432

__global__ __launch_bounds__(256, 2) void attn_kernel(const int* __restrict__ hmap) {
    const int seg = blockIdx.x;
    const int h   = blockIdx.y;
    const int b   = blockIdx.z;

    extern __shared__ __align__(16) char smraw[];
    const uint32_t smb = smem_u32(smraw);
    __shared__ int toks[128];

    const int tid  = threadIdx.x;
    const int warp = tid >> 5;
    const int lane = tid & 31;

    if (tid < 128) toks[tid] = hmap[seg * 128 + tid];
    __syncthreads();

    // ---- gather: 6 parts (Qh,Ql,Kh,Kl,Vh,Vl) x 128 rows x 8 x 16B ----
#pragma unroll
    for (int n = 0; n < 24; n++) {
        const int c   = tid + 256 * n;
        const int p   = c >> 10;
        const int rem = c & 1023;
        const int row = rem >> 3;
        const int ch  = rem & 7;
        const int tensor = p >> 1;
        const __nv_bfloat16* base = (p & 1) ? g_qkv_lo : g_qkv_hi;
        const __nv_bfloat16* s = base +
            ((((size_t)tensor * Bc + b) * Hc + h) * Mc + toks[row]) * HDc + ch * 8;
        cp_async16(smb + (uint32_t)p * 18432u + (uint32_t)(row * 144 + ch * 16), s);
    }
    CP_COMMIT();
    CP_WAIT0();
    __syncthreads();

    const int w16 = warp * 16;
    const int sub = lane >> 3;
    const int r8  = lane & 7;

    // ---- S = Q K^T (rows w16..w16+15, all 128 cols) ----
    const uint32_t aq = smb + (uint32_t)((w16 + (sub & 1) * 8 + r8) * 144 + (sub >> 1) * 16);
    uint32_t bk[8];
#pragma unroll
    for (int np = 0; np < 8; np++)
        bk[np] = smb + 36864u + (uint32_t)((np * 16 + (sub >> 1) * 8 + r8) * 144 + (sub & 1) * 16);

    float s_acc[16][4];
#pragma unroll
    for (int j = 0; j < 16; j++)
#pragma unroll
        for (int q = 0; q < 4; q++) s_acc[j][q] = 0.0f;

#pragma unroll
    for (int kt = 0; kt < 4; kt++) {
        const uint32_t kb = kt * 32;
        uint32_t Ah[4], Al[4], Bf[8][4];
        ldsm_x4(Ah, aq + kb);
        ldsm_x4(Al, aq + kb + 18432u);
#pragma unroll
        for (int np = 0; np < 8; np++) ldsm_x4(Bf[np], bk[np] + kb);          // Khi
#pragma unroll
        for (int np = 0; np < 8; np++) {
            mma_bf16(s_acc[2 * np],     Ah, Bf[np][0], Bf[np][1]);
            mma_bf16(s_acc[2 * np + 1], Ah, Bf[np][2], Bf[np][3]);
        }
#pragma unroll
        for (int np = 0; np < 8; np++) {
            mma_bf16(s_acc[2 * np],     Al, Bf[np][0], Bf[np][1]);
            mma_bf16(s_acc[2 * np + 1], Al, Bf[np][2], Bf[np][3]);
        }
#pragma unroll
        for (int np = 0; np < 8; np++) ldsm_x4(Bf[np], bk[np] + kb + 18432u); // Klo
#pragma unroll
        for (int np = 0; np < 8; np++) {
            mma_bf16(s_acc[2 * np],     Ah, Bf[np][0], Bf[np][1]);
            mma_bf16(s_acc[2 * np + 1], Ah, Bf[np][2], Bf[np][3]);
        }
    }

    // ---- masked softmax in fragment registers ----
    // fragment: rows r0=w16+(lane>>2) (q0,q1) and r0+8 (q2,q3); col t = 8j+2(lane&3)+(q&1)
    // mask: (s odd) && (t odd)  <=>  ((lane>>2)&1) && (q&1)
    const bool oddrow = ((lane >> 2) & 1) != 0;
    float mx0 = -1e30f, mx1 = -1e30f;
#pragma unroll
    for (int j = 0; j < 16; j++) {
#pragma unroll
        for (int q = 0; q < 4; q++) s_acc[j][q] *= SCALEc;
        if (oddrow) { s_acc[j][1] = -1e30f; s_acc[j][3] = -1e30f; }
        mx0 = fmaxf(mx0, fmaxf(s_acc[j][0], s_acc[j][1]));
        mx1 = fmaxf(mx1, fmaxf(s_acc[j][2], s_acc[j][3]));
    }
    mx0 = fmaxf(mx0, __shfl_xor_sync(0xffffffffu, mx0, 1));
    mx0 = fmaxf(mx0, __shfl_xor_sync(0xffffffffu, mx0, 2));
    mx1 = fmaxf(mx1, __shfl_xor_sync(0xffffffffu, mx1, 1));
    mx1 = fmaxf(mx1, __shfl_xor_sync(0xffffffffu, mx1, 2));

    float sum0 = 0.f, sum1 = 0.f;
#pragma unroll
    for (int j = 0; j < 16; j++) {
        s_acc[j][0] = __expf(s_acc[j][0] - mx0);
        s_acc[j][1] = __expf(s_acc[j][1] - mx0);
        s_acc[j][2] = __expf(s_acc[j][2] - mx1);
        s_acc[j][3] = __expf(s_acc[j][3] - mx1);
        sum0 += s_acc[j][0] + s_acc[j][1];
        sum1 += s_acc[j][2] + s_acc[j][3];
    }
    sum0 += __shfl_xor_sync(0xffffffffu, sum0, 1);
    sum0 += __shfl_xor_sync(0xffffffffu, sum0, 2);
    sum1 += __shfl_xor_sync(0xffffffffu, sum1, 1);
    sum1 += __shfl_xor_sync(0xffffffffu, sum1, 2);
    const float inv0 = 1.0f / sum0;
    const float inv1 = 1.0f / sum1;

    __syncthreads();   // all warps done reading Q/K before P overlay writes

    // ---- store P hi/lo into overlay (Phi at 0, Plo at 36864), stride 272B ----
    const uint32_t prow = smb + (uint32_t)((w16 + (lane >> 2)) * 272 + (lane & 3) * 4);
#pragma unroll
    for (int j = 0; j < 16; j++) {
        const float p0 = s_acc[j][0] * inv0, p1 = s_acc[j][1] * inv0;
        const float p2 = s_acc[j][2] * inv1, p3 = s_acc[j][3] * inv1;
        const __nv_bfloat16 h0 = __float2bfloat16_rn(p0), h1 = __float2bfloat16_rn(p1);
        const __nv_bfloat16 h2 = __float2bfloat16_rn(p2), h3 = __float2bfloat16_rn(p3);
        const uint32_t o0 = prow + j * 16;
        const uint32_t o1 = o0 + 8 * 272;
        asm volatile("st.shared.b32 [%0], %1;" :: "r"(o0), "r"(pack_bf16(p0, p1)) : "memory");
        asm volatile("st.shared.b32 [%0], %1;" :: "r"(o1), "r"(pack_bf16(p2, p3)) : "memory");
        asm volatile("st.shared.b32 [%0], %1;" :: "r"(o0 + 36864u),
            "r"(pack_bf16(p0 - __bfloat162float(h0), p1 - __bfloat162float(h1))) : "memory");
        asm volatile("st.shared.b32 [%0], %1;" :: "r"(o1 + 36864u),
            "r"(pack_bf16(p2 - __bfloat162float(h2), p3 - __bfloat162float(h3))) : "memory");
    }
    __syncwarp();

    // ---- out = P · V ----
    const uint32_t ap = smb + (uint32_t)((w16 + (lane & 15)) * 272 + (lane >> 4) * 16);
    const int mat = lane >> 3;
    const uint32_t vb = smb + 73728u +
        (uint32_t)(((mat & 1) * 8 + (lane & 7)) * 144 + (mat >> 1) * 16);

    float o_acc[8][4];
#pragma unroll
    for (int j = 0; j < 8; j++)
#pragma unroll
        for (int q = 0; q < 4; q++) o_acc[j][q] = 0.0f;

#pragma unroll
    for (int kt = 0; kt < 8; kt++) {
        uint32_t Ph[4], Pl[4], Vf[4][4];
        ldsm_x4(Ph, ap + kt * 32);
        ldsm_x4(Pl, ap + kt * 32 + 36864u);
#pragma unroll
        for (int vp = 0; vp < 4; vp++)
            ldsm_x4_t(Vf[vp], vb + (uint32_t)kt * 2304u + vp * 32u);          // Vhi
#pragma unroll
        for (int vp = 0; vp < 4; vp++) {
            mma_bf16(o_acc[2 * vp],     Ph, Vf[vp][0], Vf[vp][1]);
            mma_bf16(o_acc[2 * vp + 1], Ph, Vf[vp][2], Vf[vp][3]);
        }
#pragma unroll
        for (int vp = 0; vp < 4; vp++) {
            mma_bf16(o_acc[2 * vp],     Pl, Vf[vp][0], Vf[vp][1]);
            mma_bf16(o_acc[2 * vp + 1], Pl, Vf[vp][2], Vf[vp][3]);
        }
#pragma unroll
        for (int vp = 0; vp < 4; vp++)
            ldsm_x4_t(Vf[vp], vb + (uint32_t)kt * 2304u + vp * 32u + 18432u); // Vlo
#pragma unroll
        for (int vp = 0; vp < 4; vp++) {
            mma_bf16(o_acc[2 * vp],     Ph, Vf[vp][0], Vf[vp][1]);
            mma_bf16(o_acc[2 * vp + 1], Ph, Vf[vp][2], Vf[vp][3]);
        }
    }

    // ---- epilogue: write pre-split bf16 hi/lo attention output ----
    const int r0 = w16 + (lane >> 2);
    const size_t row0g = ((size_t)b * Mc + (size_t)seg * 128 + r0) * HIDc + h * 64;
    const size_t row1g = row0g + 8 * HIDc;
    const int dbase = 2 * (lane & 3);
#pragma unroll
    for (int j = 0; j < 8; j++) {
        const int d = 8 * j + dbase;
        const float a0 = o_acc[j][0], a1 = o_acc[j][1];
        const float a2 = o_acc[j][2], a3 = o_acc[j][3];
        const __nv_bfloat16 h0 = __float2bfloat16_rn(a0), h1 = __float2bfloat16_rn(a1);
        const __nv_bfloat16 h2 = __float2bfloat16_rn(a2), h3 = __float2bfloat16_rn(a3);
        *(uint32_t*)&g_attn_hi[row0g + d] = pack_bf16(a0, a1);
        *(uint32_t*)&g_attn_lo[row0g + d] =
            pack_bf16(a0 - __bfloat162float(h0), a1 - __bfloat162float(h1));
        *(uint32_t*)&g_attn_hi[row1g + d] = pack_bf16(a2, a3);
        *(uint32_t*)&g_attn_lo[row1g + d] =
            pack_bf16(a2 - __bfloat162float(h2), a3 - __bfloat162float(h3));
    }
}

// ===========================================================================
extern "C" void kernel_launch(void* const* d_in, const int* in_sizes, int n_in,
                              void* d_out, int out_size) {
    const float* x     = (const float*)d_in[0];
    const float* w_qkv = (const float*)d_in[1];
    const float* w_out = (const float*)d_in[2];
    const int*   hmap  = (const int*)d_in[3];
    float*       out   = (float*)d_out;

    cudaFuncSetAttribute(tgemm_kernel<0>, cudaFuncAttributeMaxDynamicSharedMemorySize, GEMM_SMEM);
    cudaFuncSetAttribute(tgemm_kernel<1>, cudaFuncAttributeMaxDynamicSharedMemorySize, GEMM_SMEM);
    cudaFuncSetAttribute(attn_kernel,     cudaFuncAttributeMaxDynamicSharedMemorySize, ATT_SMEM);

    __nv_bfloat16 *xhi, *xlo, *wqh, *wql, *woh, *wol, *ahi, *alo;
    cudaGetSymbolAddress((void**)&xhi, g_xhi);
    cudaGetSymbolAddress((void**)&xlo, g_xlo);
    cudaGetSymbolAddress((void**)&wqh, g_wqkv_hi);
    cudaGetSymbolAddress((void**)&wql, g_wqkv_lo);
    cudaGetSymbolAddress((void**)&woh, g_wout_hi);
    cudaGetSymbolAddress((void**)&wol, g_wout_lo);
    cudaGetSymbolAddress((void**)&ahi, g_attn_hi);
    cudaGetSymbolAddress((void**)&alo, g_attn_lo);

    // Pre-split inputs
    {
        int n4 = (Bc * Mc * HIDc) / 4;
        split_kernel<<<(n4 + 255) / 256, 256>>>(x, xhi, xlo, n4);
        n4 = (3 * HIDc * HIDc) / 4;
        split_kernel<<<(n4 + 255) / 256, 256>>>(w_qkv, wqh, wql, n4);
        n4 = (HIDc * HIDc) / 4;
        split_kernel<<<(n4 + 255) / 256, 256>>>(w_out, woh, wol, n4);
    }
    // QKV projection (emits pre-split bf16 hi/lo Q/K/V)
    {
        dim3 grid(3072 / 128, (Bc * Mc) / 128);
        tgemm_kernel<0><<<grid, 256, GEMM_SMEM>>>(xhi, xlo, wqh, wql, nullptr);
    }
    // Tensor-core Hilbert attention
    {
        dim3 grid(NSEGc, Hc, Bc);
        attn_kernel<<<grid, 256, ATT_SMEM>>>(hmap);
    }
    // Output projection
    {
        dim3 grid(HIDc / 128, (Bc * Mc) / 128);
        tgemm_kernel<1><<<grid, 256, GEMM_SMEM>>>(ahi, alo, woh, wol, out);
    }
}

// round 8
// speedup vs baseline: 4.9136x; 1.4918x over previous
#include <cuda_runtime.h>
#include <cuda_fp16.h>
#include <cstdint>

// Problem constants
#define Bc    4
#define Mc    4096
#define HIDc  1024
#define Hc    16
#define HDc   64
#define NSEGc 32
#define SCALEc 0.125f

// ---------------------------------------------------------------------------
// Static device scratch (allocation-free per harness rules)
// ---------------------------------------------------------------------------
__device__ __half g_qkv_hi[(size_t)3 * Bc * Hc * Mc * HDc];  // [c][b][h][m][d]
__device__ __half g_qkv_lo[(size_t)Bc * Hc * Mc * HDc];      // Q lo only
__device__ __half g_xhi[(size_t)Bc * Mc * HIDc];
__device__ __half g_xlo[(size_t)Bc * Mc * HIDc];
__device__ __half g_wqkv_hi[(size_t)3 * HIDc * HIDc];
__device__ __half g_wout_hi[(size_t)HIDc * HIDc];
__device__ __half g_attn_hi[(size_t)Bc * Mc * HIDc];
__device__ __half g_attn_lo[(size_t)Bc * Mc * HIDc];

// ===========================================================================
// Helpers
// ===========================================================================
__device__ __forceinline__ uint32_t smem_u32(const void* p) {
    uint32_t a;
    asm("{ .reg .u64 t; cvta.to.shared.u64 t, %1; cvt.u32.u64 %0, t; }"
        : "=r"(a) : "l"(p));
    return a;
}

__device__ __forceinline__ void ldsm_x4(uint32_t* r, uint32_t addr) {
    asm volatile("ldmatrix.sync.aligned.m8n8.x4.shared.b16 {%0,%1,%2,%3}, [%4];"
                 : "=r"(r[0]), "=r"(r[1]), "=r"(r[2]), "=r"(r[3]) : "r"(addr));
}
__device__ __forceinline__ void ldsm_x4_t(uint32_t* r, uint32_t addr) {
    asm volatile("ldmatrix.sync.aligned.m8n8.x4.trans.shared.b16 {%0,%1,%2,%3}, [%4];"
                 : "=r"(r[0]), "=r"(r[1]), "=r"(r[2]), "=r"(r[3]) : "r"(addr));
}

__device__ __forceinline__ void mma_f16(float* c, const uint32_t* a,
                                        uint32_t b0, uint32_t b1) {
    asm volatile(
        "mma.sync.aligned.m16n8k16.row.col.f32.f16.f16.f32 "
        "{%0,%1,%2,%3}, {%4,%5,%6,%7}, {%8,%9}, {%0,%1,%2,%3};"
        : "+f"(c[0]), "+f"(c[1]), "+f"(c[2]), "+f"(c[3])
        : "r"(a[0]), "r"(a[1]), "r"(a[2]), "r"(a[3]), "r"(b0), "r"(b1));
}

__device__ __forceinline__ void cp_async16(uint32_t dst, const void* src) {
    asm volatile("cp.async.cg.shared.global [%0], [%1], 16;"
                 :: "r"(dst), "l"(src) : "memory");
}
#define CP_COMMIT() asm volatile("cp.async.commit_group;" ::: "memory")
#define CP_WAIT0()  asm volatile("cp.async.wait_group 0;" ::: "memory")
#define CP_WAIT1()  asm volatile("cp.async.wait_group 1;" ::: "memory")

__device__ __forceinline__ uint32_t pack_f16(float x, float y) {
    __half2 v = __halves2half2(__float2half_rn(x), __float2half_rn(y));
    return *reinterpret_cast<uint32_t*>(&v);
}

// ===========================================================================
// Pre-split kernels: fp32 -> fp16 hi (+ optional lo residual)
// ===========================================================================
template <int WRITE_LO>
__global__ __launch_bounds__(256) void split_kernel(const float* __restrict__ src,
                                                    __half* __restrict__ hi,
                                                    __half* __restrict__ lo,
                                                    int n4) {
    const int i = blockIdx.x * 256 + threadIdx.x;
    if (i >= n4) return;
    const float4 v = ((const float4*)src)[i];
    const float* f = &v.x;
    __half h[4];
#pragma unroll
    for (int j = 0; j < 4; j++) h[j] = __float2half_rn(f[j]);
    ((__half2*)hi)[2 * i]     = __halves2half2(h[0], h[1]);
    ((__half2*)hi)[2 * i + 1] = __halves2half2(h[2], h[3]);
    if (WRITE_LO) {
        __half l[4];
#pragma unroll
        for (int j = 0; j < 4; j++) l[j] = __float2half_rn(f[j] - __half2float(h[j]));
        ((__half2*)lo)[2 * i]     = __halves2half2(l[0], l[1]);
        ((__half2*)lo)[2 * i + 1] = __halves2half2(l[2], l[3]);
    }
}

// ===========================================================================
// fp16 2-term tensor GEMM: C = A·W^T with A = Ahi + Alo, W = Whi (uncorrected).
// 128x128 tile, K-chunk 32, 256 threads, warp grid 4(m) x 2(n).
// 3-stage cp.async pipeline; 3 SMEM tiles per stage (Ahi, Alo, Bhi).
// MODE 0: epilogue splits to fp16 and scatters into g_qkv_hi (+lo for Q).
// MODE 1: fp32 row-major out.
// ===========================================================================
#define TK        32
#define NITER     (HIDc / TK)
#define LDSTR     40                       // fp16 elems per SMEM row (80 B)
#define TILE_HB   (128 * LDSTR * 2)        // 10240 B
#define STAGE_B   (3 * TILE_HB)            // 30720 B
#define GEMM_SMEM (3 * STAGE_B)            // 92160 B

template <int MODE>
__global__ __launch_bounds__(256, 2) void tgemm_kernel(
        const __half* __restrict__ Ahi_g, const __half* __restrict__ Alo_g,
        const __half* __restrict__ Bhi_g, float* __restrict__ Cout) {
    extern __shared__ __align__(16) char smraw[];
    const uint32_t smb = smem_u32(smraw);

    const int tid  = threadIdx.x;
    const int wid  = tid >> 5;
    const int lane = tid & 31;
    const int row0 = blockIdx.y * 128;
    const int col0 = blockIdx.x * 128;
    const int warp_m = wid & 3;
    const int warp_n = wid >> 2;

    // ---- cp.async streams: 6 per thread (3 tiles x 2 chunks) ----
    const __half* src[6];
    uint32_t rel[6];
#pragma unroll
    for (int t = 0; t < 2; t++) {
        const int ci  = tid + 256 * t;
        const int row = ci >> 2;
        const int c16 = ci & 3;
        const size_t offA = (size_t)(row0 + row) * HIDc + c16 * 8;
        const size_t offB = (size_t)(col0 + row) * HIDc + c16 * 8;
        const uint32_t so = (uint32_t)(row * (LDSTR * 2) + c16 * 16);
        src[3 * t + 0] = Ahi_g + offA;  rel[3 * t + 0] = 0 * TILE_HB + so;
        src[3 * t + 1] = Alo_g + offA;  rel[3 * t + 1] = 1 * TILE_HB + so;
        src[3 * t + 2] = Bhi_g + offB;  rel[3 * t + 2] = 2 * TILE_HB + so;
    }

    const int sub = lane >> 3;
    const int r8  = lane & 7;
    uint32_t a_lm[2], b_lm[4];
#pragma unroll
    for (int mt = 0; mt < 2; mt++) {
        const int row = warp_m * 32 + mt * 16 + (sub & 1) * 8 + r8;
        a_lm[mt] = smb + row * (LDSTR * 2) + (sub >> 1) * 16;
    }
#pragma unroll
    for (int np = 0; np < 4; np++) {
        const int row = warp_n * 64 + np * 16 + (sub >> 1) * 8 + r8;
        b_lm[np] = smb + row * (LDSTR * 2) + (sub & 1) * 16;
    }

    float acc[2][8][4];
#pragma unroll
    for (int i = 0; i < 2; i++)
#pragma unroll
        for (int j = 0; j < 8; j++)
#pragma unroll
            for (int q = 0; q < 4; q++) acc[i][j][q] = 0.0f;

    // ---- prologue: stages 0 and 1 ----
#pragma unroll
    for (int j = 0; j < 6; j++) cp_async16(smb + rel[j], src[j]);
    CP_COMMIT();
#pragma unroll
    for (int j = 0; j < 6; j++) {
        src[j] += TK;
        cp_async16(smb + STAGE_B + rel[j], src[j]);
    }
    CP_COMMIT();

    for (int it = 0; it < NITER; it++) {
        if (it + 1 < NITER) { CP_WAIT1(); } else { CP_WAIT0(); }
        __syncthreads();
        const uint32_t stg = (uint32_t)(it % 3) * STAGE_B;

        if (it + 2 < NITER) {
            const uint32_t nst = smb + (uint32_t)((it + 2) % 3) * STAGE_B;
#pragma unroll
            for (int j = 0; j < 6; j++) {
                src[j] += TK;
                cp_async16(nst + rel[j], src[j]);
            }
            CP_COMMIT();
        }

#pragma unroll
        for (int k16 = 0; k16 < 2; k16++) {
            const uint32_t kb = stg + k16 * 32;
            uint32_t Ah[2][4], Al[2][4], Bf[4][4];
#pragma unroll
            for (int mt = 0; mt < 2; mt++) {
                ldsm_x4(Ah[mt], a_lm[mt] + kb);
                ldsm_x4(Al[mt], a_lm[mt] + kb + 1 * TILE_HB);
            }
#pragma unroll
            for (int np = 0; np < 4; np++)
                ldsm_x4(Bf[np], b_lm[np] + kb + 2 * TILE_HB);
#pragma unroll
            for (int mt = 0; mt < 2; mt++)
#pragma unroll
                for (int np = 0; np < 4; np++) {
                    mma_f16(acc[mt][2 * np],     Ah[mt], Bf[np][0], Bf[np][1]);
                    mma_f16(acc[mt][2 * np + 1], Ah[mt], Bf[np][2], Bf[np][3]);
                }
#pragma unroll
            for (int mt = 0; mt < 2; mt++)
#pragma unroll
                for (int np = 0; np < 4; np++) {
                    mma_f16(acc[mt][2 * np],     Al[mt], Bf[np][0], Bf[np][1]);
                    mma_f16(acc[mt][2 * np + 1], Al[mt], Bf[np][2], Bf[np][3]);
                }
        }
    }

    // ---- epilogue ----
    const int rbase = row0 + warp_m * 32 + (lane >> 2);
    const int cbase = col0 + warp_n * 64 + 2 * (lane & 3);
#pragma unroll
    for (int mt = 0; mt < 2; mt++) {
#pragma unroll
        for (int nt = 0; nt < 8; nt++) {
            const int c = cbase + nt * 8;
#pragma unroll
            for (int half = 0; half < 2; half++) {
                const int r = rbase + mt * 16 + half * 8;
                const float vx = acc[mt][nt][2 * half];
                const float vy = acc[mt][nt][2 * half + 1];
                if (MODE == 0) {
                    const int b  = r >> 12;
                    const int m  = r & 4095;
                    const int cc = c >> 10;
                    const int h  = (c & 1023) >> 6;
                    const int d  = c & 63;
                    const size_t base = (((size_t)b * Hc + h) * Mc + m) * HDc + d;
                    const size_t idx  = (size_t)cc * (Bc * Hc * Mc * HDc) + base;
                    *(uint32_t*)&g_qkv_hi[idx] = pack_f16(vx, vy);
                    if (cc == 0) {   // Q lo residual (activation-side correction)
                        const __half hx = __float2half_rn(vx);
                        const __half hy = __float2half_rn(vy);
                        *(uint32_t*)&g_qkv_lo[base] =
                            pack_f16(vx - __half2float(hx), vy - __half2float(hy));
                    }
                } else {
                    *(float2*)&Cout[(size_t)r * HIDc + c] = make_float2(vx, vy);
                }
            }
        }
    }
}

// ===========================================================================
// Tensor-core attention (fp16 2-term): one block per (seg,h,b), 8 warps.
// S = (Qh+Ql)·Kh^T, in-register masked softmax, out = (Ph+Pl)·Vh.
// SMEM: gather Qh@0, Ql@18432, Kh@36864, Vh@69632.
//       P overlay: Ph@0, Pl@34816 (over Qh/Ql/Kh after S-phase).
// ===========================================================================
#define ATT_SMEM 88064

__global__ __launch_bounds__(256, 2) void attn_kernel(const int* __restrict__ hmap) {
    const int seg = blockIdx.x;
    const int h   = blockIdx.y;
    const int b   = blockIdx.z;

    extern __shared__ __align__(16) char smraw[];
    const uint32_t smb = smem_u32(smraw);
    __shared__ int toks[128];

    const int tid  = threadIdx.x;
    const int warp = tid >> 5;
    const int lane = tid & 31;

    if (tid < 128) toks[tid] = hmap[seg * 128 + tid];
    __syncthreads();

    // ---- gather: 4 parts (Qh,Ql,Kh,Vh) x 128 rows x 8 x 16B ----
#pragma unroll
    for (int n = 0; n < 16; n++) {
        const int c   = tid + 256 * n;
        const int p   = c >> 10;
        const int rem = c & 1023;
        const int row = rem >> 3;
        const int ch  = rem & 7;
        const int tensor = (p == 3) ? 2 : (p >> 1);   // 0,1 -> Q; 2 -> K; 3 -> V
        const __half* base = (p == 1) ? g_qkv_lo
            : g_qkv_hi + (size_t)tensor * (Bc * Hc * Mc * HDc);
        const __half* s = base +
            (((size_t)b * Hc + h) * Mc + toks[row]) * HDc + ch * 8;
        const uint32_t dst = (p == 3) ? 69632u : (uint32_t)p * 18432u;
        cp_async16(smb + dst + (uint32_t)(row * 144 + ch * 16), s);
    }
    CP_COMMIT();
    CP_WAIT0();
    __syncthreads();

    const int w16 = warp * 16;
    const int sub = lane >> 3;
    const int r8  = lane & 7;

    // ---- S = Q K^T ----
    const uint32_t aq = smb + (uint32_t)((w16 + (sub & 1) * 8 + r8) * 144 + (sub >> 1) * 16);
    uint32_t bk[8];
#pragma unroll
    for (int np = 0; np < 8; np++)
        bk[np] = smb + 36864u + (uint32_t)((np * 16 + (sub >> 1) * 8 + r8) * 144 + (sub & 1) * 16);

    float s_acc[16][4];
#pragma unroll
    for (int j = 0; j < 16; j++)
#pragma unroll
        for (int q = 0; q < 4; q++) s_acc[j][q] = 0.0f;

#pragma unroll
    for (int kt = 0; kt < 4; kt++) {
        const uint32_t kb = kt * 32;
        uint32_t Ah[4], Al[4], Bf[8][4];
        ldsm_x4(Ah, aq + kb);
        ldsm_x4(Al, aq + kb + 18432u);
#pragma unroll
        for (int np = 0; np < 8; np++) ldsm_x4(Bf[np], bk[np] + kb);   // Kh
#pragma unroll
        for (int np = 0; np < 8; np++) {
            mma_f16(s_acc[2 * np],     Ah, Bf[np][0], Bf[np][1]);
            mma_f16(s_acc[2 * np + 1], Ah, Bf[np][2], Bf[np][3]);
        }
#pragma unroll
        for (int np = 0; np < 8; np++) {
            mma_f16(s_acc[2 * np],     Al, Bf[np][0], Bf[np][1]);
            mma_f16(s_acc[2 * np + 1], Al, Bf[np][2], Bf[np][3]);
        }
    }

    // ---- masked softmax in fragment registers ----
    const bool oddrow = ((lane >> 2) & 1) != 0;
    float mx0 = -1e30f, mx1 = -1e30f;
#pragma unroll
    for (int j = 0; j < 16; j++) {
#pragma unroll
        for (int q = 0; q < 4; q++) s_acc[j][q] *= SCALEc;
        if (oddrow) { s_acc[j][1] = -1e30f; s_acc[j][3] = -1e30f; }
        mx0 = fmaxf(mx0, fmaxf(s_acc[j][0], s_acc[j][1]));
        mx1 = fmaxf(mx1, fmaxf(s_acc[j][2], s_acc[j][3]));
    }
    mx0 = fmaxf(mx0, __shfl_xor_sync(0xffffffffu, mx0, 1));
    mx0 = fmaxf(mx0, __shfl_xor_sync(0xffffffffu, mx0, 2));
    mx1 = fmaxf(mx1, __shfl_xor_sync(0xffffffffu, mx1, 1));
    mx1 = fmaxf(mx1, __shfl_xor_sync(0xffffffffu, mx1, 2));

    float sum0 = 0.f, sum1 = 0.f;
#pragma unroll
    for (int j = 0; j < 16; j++) {
        s_acc[j][0] = __expf(s_acc[j][0] - mx0);
        s_acc[j][1] = __expf(s_acc[j][1] - mx0);
        s_acc[j][2] = __expf(s_acc[j][2] - mx1);
        s_acc[j][3] = __expf(s_acc[j][3] - mx1);
        sum0 += s_acc[j][0] + s_acc[j][1];
        sum1 += s_acc[j][2] + s_acc[j][3];
    }
    sum0 += __shfl_xor_sync(0xffffffffu, sum0, 1);
    sum0 += __shfl_xor_sync(0xffffffffu, sum0, 2);
    sum1 += __shfl_xor_sync(0xffffffffu, sum1, 1);
    sum1 += __shfl_xor_sync(0xffffffffu, sum1, 2);
    const float inv0 = 1.0f / sum0;
    const float inv1 = 1.0f / sum1;

    __syncthreads();   // all warps done reading Q/K before P overlay writes

    // ---- store P hi/lo into overlay (Ph@0, Pl@34816), row stride 272B ----
    const uint32_t prow = smb + (uint32_t)((w16 + (lane >> 2)) * 272 + (lane & 3) * 4);
#pragma unroll
    for (int j = 0; j < 16; j++) {
        const float p0 = s_acc[j][0] * inv0, p1 = s_acc[j][1] * inv0;
        const float p2 = s_acc[j][2] * inv1, p3 = s_acc[j][3] * inv1;
        const __half h0 = __float2half_rn(p0), h1 = __float2half_rn(p1);
        const __half h2 = __float2half_rn(p2), h3 = __float2half_rn(p3);
        const uint32_t o0 = prow + j * 16;
        const uint32_t o1 = o0 + 8 * 272;
        asm volatile("st.shared.b32 [%0], %1;" :: "r"(o0), "r"(pack_f16(p0, p1)) : "memory");
        asm volatile("st.shared.b32 [%0], %1;" :: "r"(o1), "r"(pack_f16(p2, p3)) : "memory");
        asm volatile("st.shared.b32 [%0], %1;" :: "r"(o0 + 34816u),
            "r"(pack_f16(p0 - __half2float(h0), p1 - __half2float(h1))) : "memory");
        asm volatile("st.shared.b32 [%0], %1;" :: "r"(o1 + 34816u),
            "r"(pack_f16(p2 - __half2float(h2), p3 - __half2float(h3))) : "memory");
    }
    __syncthreads();   // P visible to ldmatrix across the block

    // ---- out = P · V ----
    const uint32_t ap = smb + (uint32_t)((w16 + (lane & 15)) * 272 + (lane >> 4) * 16);
    const int mat = lane >> 3;
    const uint32_t vb = smb + 69632u +
        (uint32_t)(((mat & 1) * 8 + (lane & 7)) * 144 + (mat >> 1) * 16);

    float o_acc[8][4];
#pragma unroll
    for (int j = 0; j < 8; j++)
#pragma unroll
        for (int q = 0; q < 4; q++) o_acc[j][q] = 0.0f;

#pragma unroll
    for (int kt = 0; kt < 8; kt++) {
        uint32_t Ph[4], Pl[4], Vf[4][4];
        ldsm_x4(Ph, ap + kt * 32);
        ldsm_x4(Pl, ap + kt * 32 + 34816u);
#pragma unroll
        for (int vp = 0; vp < 4; vp++)
            ldsm_x4_t(Vf[vp], vb + (uint32_t)kt * 2304u + vp * 32u);   // Vh
#pragma unroll
        for (int vp = 0; vp < 4; vp++) {
            mma_f16(o_acc[2 * vp],     Ph, Vf[vp][0], Vf[vp][1]);
            mma_f16(o_acc[2 * vp + 1], Ph, Vf[vp][2], Vf[vp][3]);
        }
#pragma unroll
        for (int vp = 0; vp < 4; vp++) {
            mma_f16(o_acc[2 * vp],     Pl, Vf[vp][0], Vf[vp][1]);
            mma_f16(o_acc[2 * vp + 1], Pl, Vf[vp][2], Vf[vp][3]);
        }
    }

    // ---- epilogue: write pre-split fp16 hi/lo attention output ----
    const int r0 = w16 + (lane >> 2);
    const size_t row0g = ((size_t)b * Mc + (size_t)seg * 128 + r0) * HIDc + h * 64;
    const size_t row1g = row0g + 8 * HIDc;
    const int dbase = 2 * (lane & 3);
#pragma unroll
    for (int j = 0; j < 8; j++) {
        const int d = 8 * j + dbase;
        const float a0 = o_acc[j][0], a1 = o_acc[j][1];
        const float a2 = o_acc[j][2], a3 = o_acc[j][3];
        const __half h0 = __float2half_rn(a0), h1 = __float2half_rn(a1);
        const __half h2 = __float2half_rn(a2), h3 = __float2half_rn(a3);
        *(uint32_t*)&g_attn_hi[row0g + d] = pack_f16(a0, a1);
        *(uint32_t*)&g_attn_lo[row0g + d] =
            pack_f16(a0 - __half2float(h0), a1 - __half2float(h1));
        *(uint32_t*)&g_attn_hi[row1g + d] = pack_f16(a2, a3);
        *(uint32_t*)&g_attn_lo[row1g + d] =
            pack_f16(a2 - __half2float(h2), a3 - __half2float(h3));
    }
}

// ===========================================================================
extern "C" void kernel_launch(void* const* d_in, const int* in_sizes, int n_in,
                              void* d_out, int out_size) {
    const float* x     = (const float*)d_in[0];
    const float* w_qkv = (const float*)d_in[1];
    const float* w_out = (const float*)d_in[2];
    const int*   hmap  = (const int*)d_in[3];
    float*       out   = (float*)d_out;

    cudaFuncSetAttribute(tgemm_kernel<0>, cudaFuncAttributeMaxDynamicSharedMemorySize, GEMM_SMEM);
    cudaFuncSetAttribute(tgemm_kernel<1>, cudaFuncAttributeMaxDynamicSharedMemorySize, GEMM_SMEM);
    cudaFuncSetAttribute(attn_kernel,     cudaFuncAttributeMaxDynamicSharedMemorySize, ATT_SMEM);

    __half *xhi, *xlo, *wqh, *woh, *ahi, *alo;
    cudaGetSymbolAddress((void**)&xhi, g_xhi);
    cudaGetSymbolAddress((void**)&xlo, g_xlo);
    cudaGetSymbolAddress((void**)&wqh, g_wqkv_hi);
    cudaGetSymbolAddress((void**)&woh, g_wout_hi);
    cudaGetSymbolAddress((void**)&ahi, g_attn_hi);
    cudaGetSymbolAddress((void**)&alo, g_attn_lo);

    // Pre-split: x -> hi+lo; weights -> hi only
    {
        int n4 = (Bc * Mc * HIDc) / 4;
        split_kernel<1><<<(n4 + 255) / 256, 256>>>(x, xhi, xlo, n4);
        n4 = (3 * HIDc * HIDc) / 4;
        split_kernel<0><<<(n4 + 255) / 256, 256>>>(w_qkv, wqh, nullptr, n4);
        n4 = (HIDc * HIDc) / 4;
        split_kernel<0><<<(n4 + 255) / 256, 256>>>(w_out, woh, nullptr, n4);
    }
    // QKV projection (emits fp16 Q hi/lo, K hi, V hi)
    {
        dim3 grid(3072 / 128, (Bc * Mc) / 128);
        tgemm_kernel<0><<<grid, 256, GEMM_SMEM>>>(xhi, xlo, wqh, nullptr);
    }
    // Tensor-core Hilbert attention
    {
        dim3 grid(NSEGc, Hc, Bc);
        attn_kernel<<<grid, 256, ATT_SMEM>>>(hmap);
    }
    // Output projection
    {
        dim3 grid(HIDc / 128, (Bc * Mc) / 128);
        tgemm_kernel<1><<<grid, 256, GEMM_SMEM>>>(ahi, alo, woh, out);
    }
}

// round 9
// speedup vs baseline: 5.9292x; 1.2067x over previous
#include <cuda_runtime.h>
#include <cuda_fp16.h>
#include <cstdint>

// Problem constants
#define Bc    4
#define Mc    4096
#define HIDc  1024
#define Hc    16
#define HDc   64
#define NSEGc 32
#define SCALEc 0.125f

// ---------------------------------------------------------------------------
// Static device scratch (allocation-free per harness rules)
// ---------------------------------------------------------------------------
__device__ __half g_qkv_hi[(size_t)3 * Bc * Hc * Mc * HDc];  // [c][b][h][m][d]
__device__ __half g_qkv_lo[(size_t)Bc * Hc * Mc * HDc];      // Q lo only
__device__ __half g_xhi[(size_t)Bc * Mc * HIDc];
__device__ __half g_xlo[(size_t)Bc * Mc * HIDc];
__device__ __half g_wqkv_hi[(size_t)3 * HIDc * HIDc];
__device__ __half g_wout_hi[(size_t)HIDc * HIDc];
__device__ __half g_attn_hi[(size_t)Bc * Mc * HIDc];
__device__ __half g_attn_lo[(size_t)Bc * Mc * HIDc];

// ===========================================================================
// Helpers
// ===========================================================================
__device__ __forceinline__ uint32_t smem_u32(const void* p) {
    uint32_t a;
    asm("{ .reg .u64 t; cvta.to.shared.u64 t, %1; cvt.u32.u64 %0, t; }"
        : "=r"(a) : "l"(p));
    return a;
}

__device__ __forceinline__ void ldsm_x4(uint32_t* r, uint32_t addr) {
    asm volatile("ldmatrix.sync.aligned.m8n8.x4.shared.b16 {%0,%1,%2,%3}, [%4];"
                 : "=r"(r[0]), "=r"(r[1]), "=r"(r[2]), "=r"(r[3]) : "r"(addr));
}
__device__ __forceinline__ void ldsm_x4_t(uint32_t* r, uint32_t addr) {
    asm volatile("ldmatrix.sync.aligned.m8n8.x4.trans.shared.b16 {%0,%1,%2,%3}, [%4];"
                 : "=r"(r[0]), "=r"(r[1]), "=r"(r[2]), "=r"(r[3]) : "r"(addr));
}

__device__ __forceinline__ void mma_f16(float* c, const uint32_t* a,
                                        uint32_t b0, uint32_t b1) {
    asm volatile(
        "mma.sync.aligned.m16n8k16.row.col.f32.f16.f16.f32 "
        "{%0,%1,%2,%3}, {%4,%5,%6,%7}, {%8,%9}, {%0,%1,%2,%3};"
        : "+f"(c[0]), "+f"(c[1]), "+f"(c[2]), "+f"(c[3])
        : "r"(a[0]), "r"(a[1]), "r"(a[2]), "r"(a[3]), "r"(b0), "r"(b1));
}

__device__ __forceinline__ void cp_async16(uint32_t dst, const void* src) {
    asm volatile("cp.async.cg.shared.global [%0], [%1], 16;"
                 :: "r"(dst), "l"(src) : "memory");
}
#define CP_COMMIT() asm volatile("cp.async.commit_group;" ::: "memory")
#define CP_WAIT0()  asm volatile("cp.async.wait_group 0;" ::: "memory")
#define CP_WAIT1()  asm volatile("cp.async.wait_group 1;" ::: "memory")

__device__ __forceinline__ uint32_t pack_f16(float x, float y) {
    __half2 v = __halves2half2(__float2half_rn(x), __float2half_rn(y));
    return *reinterpret_cast<uint32_t*>(&v);
}

// ===========================================================================
// Pre-split kernels: fp32 -> fp16 hi (+ optional lo residual)
// ===========================================================================
template <int WRITE_LO>
__global__ __launch_bounds__(256) void split_kernel(const float* __restrict__ src,
                                                    __half* __restrict__ hi,
                                                    __half* __restrict__ lo,
                                                    int n4) {
    const int i = blockIdx.x * 256 + threadIdx.x;
    if (i >= n4) return;
    const float4 v = ((const float4*)src)[i];
    const float* f = &v.x;
    __half h[4];
#pragma unroll
    for (int j = 0; j < 4; j++) h[j] = __float2half_rn(f[j]);
    ((__half2*)hi)[2 * i]     = __halves2half2(h[0], h[1]);
    ((__half2*)hi)[2 * i + 1] = __halves2half2(h[2], h[3]);
    if (WRITE_LO) {
        __half l[4];
#pragma unroll
        for (int j = 0; j < 4; j++) l[j] = __float2half_rn(f[j] - __half2float(h[j]));
        ((__half2*)lo)[2 * i]     = __halves2half2(l[0], l[1]);
        ((__half2*)lo)[2 * i + 1] = __halves2half2(l[2], l[3]);
    }
}

// ===========================================================================
// fp16 tensor GEMM: C = A·W^T. TERMS=2: A = Ahi + Alo; TERMS=1: A = Ahi.
// W = Whi always. 128x128 tile, K-chunk 32, 256 threads, warps 4(m) x 2(n).
// 3-stage cp.async pipeline; 3 SMEM tiles per stage (Ahi, Alo, Bhi).
// MODE 0: epilogue scatters fp16 into g_qkv_hi (+lo when col<1024, i.e. Q).
// MODE 1: fp32 row-major out.
// ===========================================================================
#define TK        32
#define NITER     (HIDc / TK)
#define LDSTR     40                       // fp16 elems per SMEM row (80 B)
#define TILE_HB   (128 * LDSTR * 2)        // 10240 B
#define STAGE_B   (3 * TILE_HB)            // 30720 B
#define GEMM_SMEM (3 * STAGE_B)            // 92160 B

template <int MODE, int TERMS>
__global__ __launch_bounds__(256, 2) void tgemm_kernel(
        const __half* __restrict__ Ahi_g, const __half* __restrict__ Alo_g,
        const __half* __restrict__ Bhi_g, float* __restrict__ Cout,
        int col_base) {
    extern __shared__ __align__(16) char smraw[];
    const uint32_t smb = smem_u32(smraw);

    const int tid  = threadIdx.x;
    const int wid  = tid >> 5;
    const int lane = tid & 31;
    const int row0 = blockIdx.y * 128;
    const int col0 = col_base + blockIdx.x * 128;
    const int warp_m = wid & 3;
    const int warp_n = wid >> 2;

    // ---- cp.async streams: up to 6 per thread (3 tiles x 2 chunks) ----
    const __half* src[6];
    uint32_t rel[6];
#pragma unroll
    for (int t = 0; t < 2; t++) {
        const int ci  = tid + 256 * t;
        const int row = ci >> 2;
        const int c16 = ci & 3;
        const size_t offA = (size_t)(row0 + row) * HIDc + c16 * 8;
        const size_t offB = (size_t)(col0 + row) * HIDc + c16 * 8;
        const uint32_t so = (uint32_t)(row * (LDSTR * 2) + c16 * 16);
        src[3 * t + 0] = Ahi_g + offA;  rel[3 * t + 0] = 0 * TILE_HB + so;
        src[3 * t + 1] = Alo_g + offA;  rel[3 * t + 1] = 1 * TILE_HB + so;
        src[3 * t + 2] = Bhi_g + offB;  rel[3 * t + 2] = 2 * TILE_HB + so;
    }

    const int sub = lane >> 3;
    const int r8  = lane & 7;
    uint32_t a_lm[2], b_lm[4];
#pragma unroll
    for (int mt = 0; mt < 2; mt++) {
        const int row = warp_m * 32 + mt * 16 + (sub & 1) * 8 + r8;
        a_lm[mt] = smb + row * (LDSTR * 2) + (sub >> 1) * 16;
    }
#pragma unroll
    for (int np = 0; np < 4; np++) {
        const int row = warp_n * 64 + np * 16 + (sub >> 1) * 8 + r8;
        b_lm[np] = smb + row * (LDSTR * 2) + (sub & 1) * 16;
    }

    float acc[2][8][4];
#pragma unroll
    for (int i = 0; i < 2; i++)
#pragma unroll
        for (int j = 0; j < 8; j++)
#pragma unroll
            for (int q = 0; q < 4; q++) acc[i][j][q] = 0.0f;

    // ---- prologue: stages 0 and 1 ----
#pragma unroll
    for (int j = 0; j < 6; j++)
        if (TERMS == 2 || (j % 3) != 1) cp_async16(smb + rel[j], src[j]);
    CP_COMMIT();
#pragma unroll
    for (int j = 0; j < 6; j++) {
        src[j] += TK;
        if (TERMS == 2 || (j % 3) != 1) cp_async16(smb + STAGE_B + rel[j], src[j]);
    }
    CP_COMMIT();

    for (int it = 0; it < NITER; it++) {
        if (it + 1 < NITER) { CP_WAIT1(); } else { CP_WAIT0(); }
        __syncthreads();
        const uint32_t stg = (uint32_t)(it % 3) * STAGE_B;

        if (it + 2 < NITER) {
            const uint32_t nst = smb + (uint32_t)((it + 2) % 3) * STAGE_B;
#pragma unroll
            for (int j = 0; j < 6; j++) {
                src[j] += TK;
                if (TERMS == 2 || (j % 3) != 1) cp_async16(nst + rel[j], src[j]);
            }
            CP_COMMIT();
        }

#pragma unroll
        for (int k16 = 0; k16 < 2; k16++) {
            const uint32_t kb = stg + k16 * 32;
            uint32_t Ah[2][4], Al[2][4], Bf[4][4];
#pragma unroll
            for (int mt = 0; mt < 2; mt++) {
                ldsm_x4(Ah[mt], a_lm[mt] + kb);
                if (TERMS == 2) ldsm_x4(Al[mt], a_lm[mt] + kb + 1 * TILE_HB);
            }
#pragma unroll
            for (int np = 0; np < 4; np++)
                ldsm_x4(Bf[np], b_lm[np] + kb + 2 * TILE_HB);
#pragma unroll
            for (int mt = 0; mt < 2; mt++)
#pragma unroll
                for (int np = 0; np < 4; np++) {
                    mma_f16(acc[mt][2 * np],     Ah[mt], Bf[np][0], Bf[np][1]);
                    mma_f16(acc[mt][2 * np + 1], Ah[mt], Bf[np][2], Bf[np][3]);
                }
            if (TERMS == 2) {
#pragma unroll
                for (int mt = 0; mt < 2; mt++)
#pragma unroll
                    for (int np = 0; np < 4; np++) {
                        mma_f16(acc[mt][2 * np],     Al[mt], Bf[np][0], Bf[np][1]);
                        mma_f16(acc[mt][2 * np + 1], Al[mt], Bf[np][2], Bf[np][3]);
                    }
            }
        }
    }

    // ---- epilogue ----
    const int rbase = row0 + warp_m * 32 + (lane >> 2);
    const int cbase = col0 + warp_n * 64 + 2 * (lane & 3);
#pragma unroll
    for (int mt = 0; mt < 2; mt++) {
#pragma unroll
        for (int nt = 0; nt < 8; nt++) {
            const int c = cbase + nt * 8;
#pragma unroll
            for (int half = 0; half < 2; half++) {
                const int r = rbase + mt * 16 + half * 8;
                const float vx = acc[mt][nt][2 * half];
                const float vy = acc[mt][nt][2 * half + 1];
                if (MODE == 0) {
                    const int b  = r >> 12;
                    const int m  = r & 4095;
                    const int cc = c >> 10;
                    const int h  = (c & 1023) >> 6;
                    const int d  = c & 63;
                    const size_t base = (((size_t)b * Hc + h) * Mc + m) * HDc + d;
                    const size_t idx  = (size_t)cc * (Bc * Hc * Mc * HDc) + base;
                    *(uint32_t*)&g_qkv_hi[idx] = pack_f16(vx, vy);
                    if (cc == 0) {   // Q lo residual (activation-side correction)
                        const __half hx = __float2half_rn(vx);
                        const __half hy = __float2half_rn(vy);
                        *(uint32_t*)&g_qkv_lo[base] =
                            pack_f16(vx - __half2float(hx), vy - __half2float(hy));
                    }
                } else {
                    *(float2*)&Cout[(size_t)r * HIDc + c] = make_float2(vx, vy);
                }
            }
        }
    }
}

// ===========================================================================
// Tensor-core attention (fp16 2-term): one block per (seg,h,b), 8 warps.
// S = (Qh+Ql)·Kh^T, in-register masked softmax, out = (Ph+Pl)·Vh.
// SMEM: gather Qh@0, Ql@18432, Kh@36864, Vh@69632.
//       P overlay: Ph@0, Pl@34816 (over Qh/Ql/Kh after S-phase).
// ===========================================================================
#define ATT_SMEM 88064

__global__ __launch_bounds__(256, 2) void attn_kernel(const int* __restrict__ hmap) {
    const int seg = blockIdx.x;
    const int h   = blockIdx.y;
    const int b   = blockIdx.z;

    extern __shared__ __align__(16) char smraw[];
    const uint32_t smb = smem_u32(smraw);
    __shared__ int toks[128];

    const int tid  = threadIdx.x;
    const int warp = tid >> 5;
    const int lane = tid & 31;

    if (tid < 128) toks[tid] = hmap[seg * 128 + tid];
    __syncthreads();

    // ---- gather: 4 parts (Qh,Ql,Kh,Vh) x 128 rows x 8 x 16B ----
#pragma unroll
    for (int n = 0; n < 16; n++) {
        const int c   = tid + 256 * n;
        const int p   = c >> 10;
        const int rem = c & 1023;
        const int row = rem >> 3;
        const int ch  = rem & 7;
        const int tensor = (p == 3) ? 2 : (p >> 1);   // 0,1 -> Q; 2 -> K; 3 -> V
        const __half* base = (p == 1) ? g_qkv_lo
            : g_qkv_hi + (size_t)tensor * (Bc * Hc * Mc * HDc);
        const __half* s = base +
            (((size_t)b * Hc + h) * Mc + toks[row]) * HDc + ch * 8;
        const uint32_t dst = (p == 3) ? 69632u : (uint32_t)p * 18432u;
        cp_async16(smb + dst + (uint32_t)(row * 144 + ch * 16), s);
    }
    CP_COMMIT();
    CP_WAIT0();
    __syncthreads();

    const int w16 = warp * 16;
    const int sub = lane >> 3;
    const int r8  = lane & 7;

    // ---- S = Q K^T ----
    const uint32_t aq = smb + (uint32_t)((w16 + (sub & 1) * 8 + r8) * 144 + (sub >> 1) * 16);
    uint32_t bk[8];
#pragma unroll
    for (int np = 0; np < 8; np++)
        bk[np] = smb + 36864u + (uint32_t)((np * 16 + (sub >> 1) * 8 + r8) * 144 + (sub & 1) * 16);

    float s_acc[16][4];
#pragma unroll
    for (int j = 0; j < 16; j++)
#pragma unroll
        for (int q = 0; q < 4; q++) s_acc[j][q] = 0.0f;

#pragma unroll
    for (int kt = 0; kt < 4; kt++) {
        const uint32_t kb = kt * 32;
        uint32_t Ah[4], Al[4], Bf[8][4];
        ldsm_x4(Ah, aq + kb);
        ldsm_x4(Al, aq + kb + 18432u);
#pragma unroll
        for (int np = 0; np < 8; np++) ldsm_x4(Bf[np], bk[np] + kb);   // Kh
#pragma unroll
        for (int np = 0; np < 8; np++) {
            mma_f16(s_acc[2 * np],     Ah, Bf[np][0], Bf[np][1]);
            mma_f16(s_acc[2 * np + 1], Ah, Bf[np][2], Bf[np][3]);
        }
#pragma unroll
        for (int np = 0; np < 8; np++) {
            mma_f16(s_acc[2 * np],     Al, Bf[np][0], Bf[np][1]);
            mma_f16(s_acc[2 * np + 1], Al, Bf[np][2], Bf[np][3]);
        }
    }

    // ---- masked softmax in fragment registers ----
    const bool oddrow = ((lane >> 2) & 1) != 0;
    float mx0 = -1e30f, mx1 = -1e30f;
#pragma unroll
    for (int j = 0; j < 16; j++) {
#pragma unroll
        for (int q = 0; q < 4; q++) s_acc[j][q] *= SCALEc;
        if (oddrow) { s_acc[j][1] = -1e30f; s_acc[j][3] = -1e30f; }
        mx0 = fmaxf(mx0, fmaxf(s_acc[j][0], s_acc[j][1]));
        mx1 = fmaxf(mx1, fmaxf(s_acc[j][2], s_acc[j][3]));
    }
    mx0 = fmaxf(mx0, __shfl_xor_sync(0xffffffffu, mx0, 1));
    mx0 = fmaxf(mx0, __shfl_xor_sync(0xffffffffu, mx0, 2));
    mx1 = fmaxf(mx1, __shfl_xor_sync(0xffffffffu, mx1, 1));
    mx1 = fmaxf(mx1, __shfl_xor_sync(0xffffffffu, mx1, 2));

    float sum0 = 0.f, sum1 = 0.f;
#pragma unroll
    for (int j = 0; j < 16; j++) {
        s_acc[j][0] = __expf(s_acc[j][0] - mx0);
        s_acc[j][1] = __expf(s_acc[j][1] - mx0);
        s_acc[j][2] = __expf(s_acc[j][2] - mx1);
        s_acc[j][3] = __expf(s_acc[j][3] - mx1);
        sum0 += s_acc[j][0] + s_acc[j][1];
        sum1 += s_acc[j][2] + s_acc[j][3];
    }
    sum0 += __shfl_xor_sync(0xffffffffu, sum0, 1);
    sum0 += __shfl_xor_sync(0xffffffffu, sum0, 2);
    sum1 += __shfl_xor_sync(0xffffffffu, sum1, 1);
    sum1 += __shfl_xor_sync(0xffffffffu, sum1, 2);
    const float inv0 = 1.0f / sum0;
    const float inv1 = 1.0f / sum1;

    __syncthreads();   // all warps done reading Q/K before P overlay writes

    // ---- store P hi/lo into overlay (Ph@0, Pl@34816), row stride 272B ----
    const uint32_t prow = smb + (uint32_t)((w16 + (lane >> 2)) * 272 + (lane & 3) * 4);
#pragma unroll
    for (int j = 0; j < 16; j++) {
        const float p0 = s_acc[j][0] * inv0, p1 = s_acc[j][1] * inv0;
        const float p2 = s_acc[j][2] * inv1, p3 = s_acc[j][3] * inv1;
        const __half h0 = __float2half_rn(p0), h1 = __float2half_rn(p1);
        const __half h2 = __float2half_rn(p2), h3 = __float2half_rn(p3);
        const uint32_t o0 = prow + j * 16;
        const uint32_t o1 = o0 + 8 * 272;
        asm volatile("st.shared.b32 [%0], %1;" :: "r"(o0), "r"(pack_f16(p0, p1)) : "memory");
        asm volatile("st.shared.b32 [%0], %1;" :: "r"(o1), "r"(pack_f16(p2, p3)) : "memory");
        asm volatile("st.shared.b32 [%0], %1;" :: "r"(o0 + 34816u),
            "r"(pack_f16(p0 - __half2float(h0), p1 - __half2float(h1))) : "memory");
        asm volatile("st.shared.b32 [%0], %1;" :: "r"(o1 + 34816u),
            "r"(pack_f16(p2 - __half2float(h2), p3 - __half2float(h3))) : "memory");
    }
    __syncthreads();   // P visible to ldmatrix across the block

    // ---- out = P · V ----
    const uint32_t ap = smb + (uint32_t)((w16 + (lane & 15)) * 272 + (lane >> 4) * 16);
    const int mat = lane >> 3;
    const uint32_t vb = smb + 69632u +
        (uint32_t)(((mat & 1) * 8 + (lane & 7)) * 144 + (mat >> 1) * 16);

    float o_acc[8][4];
#pragma unroll
    for (int j = 0; j < 8; j++)
#pragma unroll
        for (int q = 0; q < 4; q++) o_acc[j][q] = 0.0f;

#pragma unroll
    for (int kt = 0; kt < 8; kt++) {
        uint32_t Ph[4], Pl[4], Vf[4][4];
        ldsm_x4(Ph, ap + kt * 32);
        ldsm_x4(Pl, ap + kt * 32 + 34816u);
#pragma unroll
        for (int vp = 0; vp < 4; vp++)
            ldsm_x4_t(Vf[vp], vb + (uint32_t)kt * 2304u + vp * 32u);   // Vh
#pragma unroll
        for (int vp = 0; vp < 4; vp++) {
            mma_f16(o_acc[2 * vp],     Ph, Vf[vp][0], Vf[vp][1]);
            mma_f16(o_acc[2 * vp + 1], Ph, Vf[vp][2], Vf[vp][3]);
        }
#pragma unroll
        for (int vp = 0; vp < 4; vp++) {
            mma_f16(o_acc[2 * vp],     Pl, Vf[vp][0], Vf[vp][1]);
            mma_f16(o_acc[2 * vp + 1], Pl, Vf[vp][2], Vf[vp][3]);
        }
    }

    // ---- epilogue: write pre-split fp16 hi/lo attention output ----
    const int r0 = w16 + (lane >> 2);
    const size_t row0g = ((size_t)b * Mc + (size_t)seg * 128 + r0) * HIDc + h * 64;
    const size_t row1g = row0g + 8 * HIDc;
    const int dbase = 2 * (lane & 3);
#pragma unroll
    for (int j = 0; j < 8; j++) {
        const int d = 8 * j + dbase;
        const float a0 = o_acc[j][0], a1 = o_acc[j][1];
        const float a2 = o_acc[j][2], a3 = o_acc[j][3];
        const __half h0 = __float2half_rn(a0), h1 = __float2half_rn(a1);
        const __half h2 = __float2half_rn(a2), h3 = __float2half_rn(a3);
        *(uint32_t*)&g_attn_hi[row0g + d] = pack_f16(a0, a1);
        *(uint32_t*)&g_attn_lo[row0g + d] =
            pack_f16(a0 - __half2float(h0), a1 - __half2float(h1));
        *(uint32_t*)&g_attn_hi[row1g + d] = pack_f16(a2, a3);
        *(uint32_t*)&g_attn_lo[row1g + d] =
            pack_f16(a2 - __half2float(h2), a3 - __half2float(h3));
    }
}

// ===========================================================================
extern "C" void kernel_launch(void* const* d_in, const int* in_sizes, int n_in,
                              void* d_out, int out_size) {
    const float* x     = (const float*)d_in[0];
    const float* w_qkv = (const float*)d_in[1];
    const float* w_out = (const float*)d_in[2];
    const int*   hmap  = (const int*)d_in[3];
    float*       out   = (float*)d_out;

    cudaFuncSetAttribute(tgemm_kernel<0, 2>, cudaFuncAttributeMaxDynamicSharedMemorySize, GEMM_SMEM);
    cudaFuncSetAttribute(tgemm_kernel<0, 1>, cudaFuncAttributeMaxDynamicSharedMemorySize, GEMM_SMEM);
    cudaFuncSetAttribute(tgemm_kernel<1, 2>, cudaFuncAttributeMaxDynamicSharedMemorySize, GEMM_SMEM);
    cudaFuncSetAttribute(attn_kernel,        cudaFuncAttributeMaxDynamicSharedMemorySize, ATT_SMEM);

    __half *xhi, *xlo, *wqh, *woh, *ahi, *alo;
    cudaGetSymbolAddress((void**)&xhi, g_xhi);
    cudaGetSymbolAddress((void**)&xlo, g_xlo);
    cudaGetSymbolAddress((void**)&wqh, g_wqkv_hi);
    cudaGetSymbolAddress((void**)&woh, g_wout_hi);
    cudaGetSymbolAddress((void**)&ahi, g_attn_hi);
    cudaGetSymbolAddress((void**)&alo, g_attn_lo);

    // Pre-split: x -> hi+lo; weights -> hi only
    {
        int n4 = (Bc * Mc * HIDc) / 4;
        split_kernel<1><<<(n4 + 255) / 256, 256>>>(x, xhi, xlo, n4);
        n4 = (3 * HIDc * HIDc) / 4;
        split_kernel<0><<<(n4 + 255) / 256, 256>>>(w_qkv, wqh, nullptr, n4);
        n4 = (HIDc * HIDc) / 4;
        split_kernel<0><<<(n4 + 255) / 256, 256>>>(w_out, woh, nullptr, n4);
    }
    // QKV projection, Q columns [0,1024): 2-term (emits Q hi+lo)
    {
        dim3 grid(HIDc / 128, (Bc * Mc) / 128);         // (8, 128)
        tgemm_kernel<0, 2><<<grid, 256, GEMM_SMEM>>>(xhi, xlo, wqh, nullptr, 0);
    }
    // QKV projection, K/V columns [1024,3072): 1-term (emits K,V hi)
    {
        dim3 grid(2048 / 128, (Bc * Mc) / 128);         // (16, 128)
        tgemm_kernel<0, 1><<<grid, 256, GEMM_SMEM>>>(xhi, xhi, wqh, nullptr, 1024);
    }
    // Tensor-core Hilbert attention
    {
        dim3 grid(NSEGc, Hc, Bc);
        attn_kernel<<<grid, 256, ATT_SMEM>>>(hmap);
    }
    // Output projection (2-term on attention activations)
    {
        dim3 grid(HIDc / 128, (Bc * Mc) / 128);         // (8, 128)
        tgemm_kernel<1, 2><<<grid, 256, GEMM_SMEM>>>(ahi, alo, woh, out, 0);
    }
}

// round 10
// speedup vs baseline: 7.0321x; 1.1860x over previous
#include <cuda_runtime.h>
#include <cuda_fp16.h>
#include <cstdint>

// Problem constants
#define Bc    4
#define Mc    4096
#define HIDc  1024
#define Hc    16
#define HDc   64
#define NSEGc 32
#define SCALEc 0.125f

// ---------------------------------------------------------------------------
// Static device scratch (allocation-free per harness rules)
// ---------------------------------------------------------------------------
__device__ __half g_qkv_hi[(size_t)3 * Bc * Hc * Mc * HDc];  // [c][b][h][m][d]
__device__ __half g_xhi[(size_t)Bc * Mc * HIDc];
__device__ __half g_wqkv_hi[(size_t)3 * HIDc * HIDc];
__device__ __half g_wout_hi[(size_t)HIDc * HIDc];
__device__ __half g_attn_hi[(size_t)Bc * Mc * HIDc];
__device__ __half g_attn_lo[(size_t)Bc * Mc * HIDc];

// ===========================================================================
// Helpers
// ===========================================================================
__device__ __forceinline__ uint32_t smem_u32(const void* p) {
    uint32_t a;
    asm("{ .reg .u64 t; cvta.to.shared.u64 t, %1; cvt.u32.u64 %0, t; }"
        : "=r"(a) : "l"(p));
    return a;
}

__device__ __forceinline__ void ldsm_x4(uint32_t* r, uint32_t addr) {
    asm volatile("ldmatrix.sync.aligned.m8n8.x4.shared.b16 {%0,%1,%2,%3}, [%4];"
                 : "=r"(r[0]), "=r"(r[1]), "=r"(r[2]), "=r"(r[3]) : "r"(addr));
}
__device__ __forceinline__ void ldsm_x4_t(uint32_t* r, uint32_t addr) {
    asm volatile("ldmatrix.sync.aligned.m8n8.x4.trans.shared.b16 {%0,%1,%2,%3}, [%4];"
                 : "=r"(r[0]), "=r"(r[1]), "=r"(r[2]), "=r"(r[3]) : "r"(addr));
}

__device__ __forceinline__ void mma_f16(float* c, const uint32_t* a,
                                        uint32_t b0, uint32_t b1) {
    asm volatile(
        "mma.sync.aligned.m16n8k16.row.col.f32.f16.f16.f32 "
        "{%0,%1,%2,%3}, {%4,%5,%6,%7}, {%8,%9}, {%0,%1,%2,%3};"
        : "+f"(c[0]), "+f"(c[1]), "+f"(c[2]), "+f"(c[3])
        : "r"(a[0]), "r"(a[1]), "r"(a[2]), "r"(a[3]), "r"(b0), "r"(b1));
}

__device__ __forceinline__ void cp_async16(uint32_t dst, const void* src) {
    asm volatile("cp.async.cg.shared.global [%0], [%1], 16;"
                 :: "r"(dst), "l"(src) : "memory");
}
#define CP_COMMIT() asm volatile("cp.async.commit_group;" ::: "memory")
#define CP_WAIT0()  asm volatile("cp.async.wait_group 0;" ::: "memory")
#define CP_WAIT1()  asm volatile("cp.async.wait_group 1;" ::: "memory")

__device__ __forceinline__ uint32_t pack_f16(float x, float y) {
    __half2 v = __halves2half2(__float2half_rn(x), __float2half_rn(y));
    return *reinterpret_cast<uint32_t*>(&v);
}

// ===========================================================================
// Pre-split kernels: fp32 -> fp16 hi (+ optional lo residual)
// ===========================================================================
template <int WRITE_LO>
__global__ __launch_bounds__(256) void split_kernel(const float* __restrict__ src,
                                                    __half* __restrict__ hi,
                                                    __half* __restrict__ lo,
                                                    int n4) {
    const int i = blockIdx.x * 256 + threadIdx.x;
    if (i >= n4) return;
    const float4 v = ((const float4*)src)[i];
    const float* f = &v.x;
    __half h[4];
#pragma unroll
    for (int j = 0; j < 4; j++) h[j] = __float2half_rn(f[j]);
    ((__half2*)hi)[2 * i]     = __halves2half2(h[0], h[1]);
    ((__half2*)hi)[2 * i + 1] = __halves2half2(h[2], h[3]);
    if (WRITE_LO) {
        __half l[4];
#pragma unroll
        for (int j = 0; j < 4; j++) l[j] = __float2half_rn(f[j] - __half2float(h[j]));
        ((__half2*)lo)[2 * i]     = __halves2half2(l[0], l[1]);
        ((__half2*)lo)[2 * i + 1] = __halves2half2(l[2], l[3]);
    }
}

// ===========================================================================
// fp16 tensor GEMM: C = A·W^T. TERMS=2: A = Ahi + Alo; TERMS=1: A = Ahi.
// W = Whi always. 128x128 tile, K-chunk 32, 256 threads, warps 4(m) x 2(n).
// 3-stage cp.async pipeline; 3 SMEM tiles per stage (Ahi, Alo, Bhi).
// MODE 0: epilogue scatters fp16 hi into g_qkv_hi.
// MODE 1: fp32 row-major out.
// ===========================================================================
#define TK        32
#define NITER     (HIDc / TK)
#define LDSTR     40                       // fp16 elems per SMEM row (80 B)
#define TILE_HB   (128 * LDSTR * 2)        // 10240 B
#define STAGE_B   (3 * TILE_HB)            // 30720 B
#define GEMM_SMEM (3 * STAGE_B)            // 92160 B

template <int MODE, int TERMS>
__global__ __launch_bounds__(256, 2) void tgemm_kernel(
        const __half* __restrict__ Ahi_g, const __half* __restrict__ Alo_g,
        const __half* __restrict__ Bhi_g, float* __restrict__ Cout) {
    extern __shared__ __align__(16) char smraw[];
    const uint32_t smb = smem_u32(smraw);

    const int tid  = threadIdx.x;
    const int wid  = tid >> 5;
    const int lane = tid & 31;
    const int row0 = blockIdx.y * 128;
    const int col0 = blockIdx.x * 128;
    const int warp_m = wid & 3;
    const int warp_n = wid >> 2;

    // ---- cp.async streams: up to 6 per thread (3 tiles x 2 chunks) ----
    const __half* src[6];
    uint32_t rel[6];
#pragma unroll
    for (int t = 0; t < 2; t++) {
        const int ci  = tid + 256 * t;
        const int row = ci >> 2;
        const int c16 = ci & 3;
        const size_t offA = (size_t)(row0 + row) * HIDc + c16 * 8;
        const size_t offB = (size_t)(col0 + row) * HIDc + c16 * 8;
        const uint32_t so = (uint32_t)(row * (LDSTR * 2) + c16 * 16);
        src[3 * t + 0] = Ahi_g + offA;  rel[3 * t + 0] = 0 * TILE_HB + so;
        src[3 * t + 1] = Alo_g + offA;  rel[3 * t + 1] = 1 * TILE_HB + so;
        src[3 * t + 2] = Bhi_g + offB;  rel[3 * t + 2] = 2 * TILE_HB + so;
    }

    const int sub = lane >> 3;
    const int r8  = lane & 7;
    uint32_t a_lm[2], b_lm[4];
#pragma unroll
    for (int mt = 0; mt < 2; mt++) {
        const int row = warp_m * 32 + mt * 16 + (sub & 1) * 8 + r8;
        a_lm[mt] = smb + row * (LDSTR * 2) + (sub >> 1) * 16;
    }
#pragma unroll
    for (int np = 0; np < 4; np++) {
        const int row = warp_n * 64 + np * 16 + (sub >> 1) * 8 + r8;
        b_lm[np] = smb + row * (LDSTR * 2) + (sub & 1) * 16;
    }

    float acc[2][8][4];
#pragma unroll
    for (int i = 0; i < 2; i++)
#pragma unroll
        for (int j = 0; j < 8; j++)
#pragma unroll
            for (int q = 0; q < 4; q++) acc[i][j][q] = 0.0f;

    // ---- prologue: stages 0 and 1 ----
#pragma unroll
    for (int j = 0; j < 6; j++)
        if (TERMS == 2 || (j % 3) != 1) cp_async16(smb + rel[j], src[j]);
    CP_COMMIT();
#pragma unroll
    for (int j = 0; j < 6; j++) {
        src[j] += TK;
        if (TERMS == 2 || (j % 3) != 1) cp_async16(smb + STAGE_B + rel[j], src[j]);
    }
    CP_COMMIT();

    for (int it = 0; it < NITER; it++) {
        if (it + 1 < NITER) { CP_WAIT1(); } else { CP_WAIT0(); }
        __syncthreads();
        const uint32_t stg = (uint32_t)(it % 3) * STAGE_B;

        if (it + 2 < NITER) {
            const uint32_t nst = smb + (uint32_t)((it + 2) % 3) * STAGE_B;
#pragma unroll
            for (int j = 0; j < 6; j++) {
                src[j] += TK;
                if (TERMS == 2 || (j % 3) != 1) cp_async16(nst + rel[j], src[j]);
            }
            CP_COMMIT();
        }

#pragma unroll
        for (int k16 = 0; k16 < 2; k16++) {
            const uint32_t kb = stg + k16 * 32;
            uint32_t Ah[2][4], Al[2][4], Bf[4][4];
#pragma unroll
            for (int mt = 0; mt < 2; mt++) {
                ldsm_x4(Ah[mt], a_lm[mt] + kb);
                if (TERMS == 2) ldsm_x4(Al[mt], a_lm[mt] + kb + 1 * TILE_HB);
            }
#pragma unroll
            for (int np = 0; np < 4; np++)
                ldsm_x4(Bf[np], b_lm[np] + kb + 2 * TILE_HB);
#pragma unroll
            for (int mt = 0; mt < 2; mt++)
#pragma unroll
                for (int np = 0; np < 4; np++) {
                    mma_f16(acc[mt][2 * np],     Ah[mt], Bf[np][0], Bf[np][1]);
                    mma_f16(acc[mt][2 * np + 1], Ah[mt], Bf[np][2], Bf[np][3]);
                }
            if (TERMS == 2) {
#pragma unroll
                for (int mt = 0; mt < 2; mt++)
#pragma unroll
                    for (int np = 0; np < 4; np++) {
                        mma_f16(acc[mt][2 * np],     Al[mt], Bf[np][0], Bf[np][1]);
                        mma_f16(acc[mt][2 * np + 1], Al[mt], Bf[np][2], Bf[np][3]);
                    }
            }
        }
    }

    // ---- epilogue ----
    const int rbase = row0 + warp_m * 32 + (lane >> 2);
    const int cbase = col0 + warp_n * 64 + 2 * (lane & 3);
#pragma unroll
    for (int mt = 0; mt < 2; mt++) {
#pragma unroll
        for (int nt = 0; nt < 8; nt++) {
            const int c = cbase + nt * 8;
#pragma unroll
            for (int half = 0; half < 2; half++) {
                const int r = rbase + mt * 16 + half * 8;
                const float vx = acc[mt][nt][2 * half];
                const float vy = acc[mt][nt][2 * half + 1];
                if (MODE == 0) {
                    const int b  = r >> 12;
                    const int m  = r & 4095;
                    const int cc = c >> 10;
                    const int h  = (c & 1023) >> 6;
                    const int d  = c & 63;
                    const size_t idx = (size_t)cc * (Bc * Hc * Mc * HDc) +
                        (((size_t)b * Hc + h) * Mc + m) * HDc + d;
                    *(uint32_t*)&g_qkv_hi[idx] = pack_f16(vx, vy);
                } else {
                    *(float2*)&Cout[(size_t)r * HIDc + c] = make_float2(vx, vy);
                }
            }
        }
    }
}

// ===========================================================================
// Tensor-core attention (fp16 1-term): one block per (seg,h,b), 8 warps.
// S = Qh·Kh^T, in-register masked softmax, out = Ph·Vh.
// SMEM: gather Qh@0, Kh@18432, Vh@36864.
//       P overlay: Ph@0 (stride 272B, 34816 B, over Qh/Kh after S-phase).
// ===========================================================================
#define ATT_SMEM 55296

__global__ __launch_bounds__(256, 2) void attn_kernel(const int* __restrict__ hmap) {
    const int seg = blockIdx.x;
    const int h   = blockIdx.y;
    const int b   = blockIdx.z;

    extern __shared__ __align__(16) char smraw[];
    const uint32_t smb = smem_u32(smraw);
    __shared__ int toks[128];

    const int tid  = threadIdx.x;
    const int warp = tid >> 5;
    const int lane = tid & 31;

    if (tid < 128) toks[tid] = hmap[seg * 128 + tid];
    __syncthreads();

    // ---- gather: 3 parts (Qh,Kh,Vh) x 128 rows x 8 x 16B ----
#pragma unroll
    for (int n = 0; n < 12; n++) {
        const int c   = tid + 256 * n;
        const int p   = c >> 10;              // 0=Q, 1=K, 2=V
        const int rem = c & 1023;
        const int row = rem >> 3;
        const int ch  = rem & 7;
        const __half* s = g_qkv_hi + (size_t)p * (Bc * Hc * Mc * HDc) +
            (((size_t)b * Hc + h) * Mc + toks[row]) * HDc + ch * 8;
        cp_async16(smb + (uint32_t)p * 18432u + (uint32_t)(row * 144 + ch * 16), s);
    }
    CP_COMMIT();
    CP_WAIT0();
    __syncthreads();

    const int w16 = warp * 16;
    const int sub = lane >> 3;
    const int r8  = lane & 7;

    // ---- S = Qh Kh^T ----
    const uint32_t aq = smb + (uint32_t)((w16 + (sub & 1) * 8 + r8) * 144 + (sub >> 1) * 16);
    uint32_t bk[8];
#pragma unroll
    for (int np = 0; np < 8; np++)
        bk[np] = smb + 18432u + (uint32_t)((np * 16 + (sub >> 1) * 8 + r8) * 144 + (sub & 1) * 16);

    float s_acc[16][4];
#pragma unroll
    for (int j = 0; j < 16; j++)
#pragma unroll
        for (int q = 0; q < 4; q++) s_acc[j][q] = 0.0f;

#pragma unroll
    for (int kt = 0; kt < 4; kt++) {
        const uint32_t kb = kt * 32;
        uint32_t Ah[4], Bf[8][4];
        ldsm_x4(Ah, aq + kb);
#pragma unroll
        for (int np = 0; np < 8; np++) ldsm_x4(Bf[np], bk[np] + kb);
#pragma unroll
        for (int np = 0; np < 8; np++) {
            mma_f16(s_acc[2 * np],     Ah, Bf[np][0], Bf[np][1]);
            mma_f16(s_acc[2 * np + 1], Ah, Bf[np][2], Bf[np][3]);
        }
    }

    // ---- masked softmax in fragment registers ----
    const bool oddrow = ((lane >> 2) & 1) != 0;
    float mx0 = -1e30f, mx1 = -1e30f;
#pragma unroll
    for (int j = 0; j < 16; j++) {
#pragma unroll
        for (int q = 0; q < 4; q++) s_acc[j][q] *= SCALEc;
        if (oddrow) { s_acc[j][1] = -1e30f; s_acc[j][3] = -1e30f; }
        mx0 = fmaxf(mx0, fmaxf(s_acc[j][0], s_acc[j][1]));
        mx1 = fmaxf(mx1, fmaxf(s_acc[j][2], s_acc[j][3]));
    }
    mx0 = fmaxf(mx0, __shfl_xor_sync(0xffffffffu, mx0, 1));
    mx0 = fmaxf(mx0, __shfl_xor_sync(0xffffffffu, mx0, 2));
    mx1 = fmaxf(mx1, __shfl_xor_sync(0xffffffffu, mx1, 1));
    mx1 = fmaxf(mx1, __shfl_xor_sync(0xffffffffu, mx1, 2));

    float sum0 = 0.f, sum1 = 0.f;
#pragma unroll
    for (int j = 0; j < 16; j++) {
        s_acc[j][0] = __expf(s_acc[j][0] - mx0);
        s_acc[j][1] = __expf(s_acc[j][1] - mx0);
        s_acc[j][2] = __expf(s_acc[j][2] - mx1);
        s_acc[j][3] = __expf(s_acc[j][3] - mx1);
        sum0 += s_acc[j][0] + s_acc[j][1];
        sum1 += s_acc[j][2] + s_acc[j][3];
    }
    sum0 += __shfl_xor_sync(0xffffffffu, sum0, 1);
    sum0 += __shfl_xor_sync(0xffffffffu, sum0, 2);
    sum1 += __shfl_xor_sync(0xffffffffu, sum1, 1);
    sum1 += __shfl_xor_sync(0xffffffffu, sum1, 2);
    const float inv0 = 1.0f / sum0;
    const float inv1 = 1.0f / sum1;

    __syncthreads();   // all warps done reading Q/K before P overlay writes

    // ---- store Ph into overlay (stride 272B) ----
    const uint32_t prow = smb + (uint32_t)((w16 + (lane >> 2)) * 272 + (lane & 3) * 4);
#pragma unroll
    for (int j = 0; j < 16; j++) {
        const float p0 = s_acc[j][0] * inv0, p1 = s_acc[j][1] * inv0;
        const float p2 = s_acc[j][2] * inv1, p3 = s_acc[j][3] * inv1;
        const uint32_t o0 = prow + j * 16;
        const uint32_t o1 = o0 + 8 * 272;
        asm volatile("st.shared.b32 [%0], %1;" :: "r"(o0), "r"(pack_f16(p0, p1)) : "memory");
        asm volatile("st.shared.b32 [%0], %1;" :: "r"(o1), "r"(pack_f16(p2, p3)) : "memory");
    }
    __syncthreads();   // P visible to ldmatrix across the block

    // ---- out = Ph · Vh ----
    const uint32_t ap = smb + (uint32_t)((w16 + (lane & 15)) * 272 + (lane >> 4) * 16);
    const int mat = lane >> 3;
    const uint32_t vb = smb + 36864u +
        (uint32_t)(((mat & 1) * 8 + (lane & 7)) * 144 + (mat >> 1) * 16);

    float o_acc[8][4];
#pragma unroll
    for (int j = 0; j < 8; j++)
#pragma unroll
        for (int q = 0; q < 4; q++) o_acc[j][q] = 0.0f;

#pragma unroll
    for (int kt = 0; kt < 8; kt++) {
        uint32_t Ph[4], Vf[4][4];
        ldsm_x4(Ph, ap + kt * 32);
#pragma unroll
        for (int vp = 0; vp < 4; vp++)
            ldsm_x4_t(Vf[vp], vb + (uint32_t)kt * 2304u + vp * 32u);
#pragma unroll
        for (int vp = 0; vp < 4; vp++) {
            mma_f16(o_acc[2 * vp],     Ph, Vf[vp][0], Vf[vp][1]);
            mma_f16(o_acc[2 * vp + 1], Ph, Vf[vp][2], Vf[vp][3]);
        }
    }

    // ---- epilogue: write pre-split fp16 hi/lo attention output ----
    const int r0 = w16 + (lane >> 2);
    const size_t row0g = ((size_t)b * Mc + (size_t)seg * 128 + r0) * HIDc + h * 64;
    const size_t row1g = row0g + 8 * HIDc;
    const int dbase = 2 * (lane & 3);
#pragma unroll
    for (int j = 0; j < 8; j++) {
        const int d = 8 * j + dbase;
        const float a0 = o_acc[j][0], a1 = o_acc[j][1];
        const float a2 = o_acc[j][2], a3 = o_acc[j][3];
        const __half h0 = __float2half_rn(a0), h1 = __float2half_rn(a1);
        const __half h2 = __float2half_rn(a2), h3 = __float2half_rn(a3);
        *(uint32_t*)&g_attn_hi[row0g + d] = pack_f16(a0, a1);
        *(uint32_t*)&g_attn_lo[row0g + d] =
            pack_f16(a0 - __half2float(h0), a1 - __half2float(h1));
        *(uint32_t*)&g_attn_hi[row1g + d] = pack_f16(a2, a3);
        *(uint32_t*)&g_attn_lo[row1g + d] =
            pack_f16(a2 - __half2float(h2), a3 - __half2float(h3));
    }
}

// ===========================================================================
extern "C" void kernel_launch(void* const* d_in, const int* in_sizes, int n_in,
                              void* d_out, int out_size) {
    const float* x     = (const float*)d_in[0];
    const float* w_qkv = (const float*)d_in[1];
    const float* w_out = (const float*)d_in[2];
    const int*   hmap  = (const int*)d_in[3];
    float*       out   = (float*)d_out;

    cudaFuncSetAttribute(tgemm_kernel<0, 1>, cudaFuncAttributeMaxDynamicSharedMemorySize, GEMM_SMEM);
    cudaFuncSetAttribute(tgemm_kernel<1, 2>, cudaFuncAttributeMaxDynamicSharedMemorySize, GEMM_SMEM);
    cudaFuncSetAttribute(attn_kernel,        cudaFuncAttributeMaxDynamicSharedMemorySize, ATT_SMEM);

    __half *xhi, *wqh, *woh, *ahi, *alo;
    cudaGetSymbolAddress((void**)&xhi, g_xhi);
    cudaGetSymbolAddress((void**)&wqh, g_wqkv_hi);
    cudaGetSymbolAddress((void**)&woh, g_wout_hi);
    cudaGetSymbolAddress((void**)&ahi, g_attn_hi);
    cudaGetSymbolAddress((void**)&alo, g_attn_lo);

    // Pre-split: all inputs -> fp16 hi only
    {
        int n4 = (Bc * Mc * HIDc) / 4;
        split_kernel<0><<<(n4 + 255) / 256, 256>>>(x, xhi, nullptr, n4);
        n4 = (3 * HIDc * HIDc) / 4;
        split_kernel<0><<<(n4 + 255) / 256, 256>>>(w_qkv, wqh, nullptr, n4);
        n4 = (HIDc * HIDc) / 4;
        split_kernel<0><<<(n4 + 255) / 256, 256>>>(w_out, woh, nullptr, n4);
    }
    // QKV projection: single 1-term launch over all 3072 columns
    {
        dim3 grid(3072 / 128, (Bc * Mc) / 128);         // (24, 128)
        tgemm_kernel<0, 1><<<grid, 256, GEMM_SMEM>>>(xhi, xhi, wqh, nullptr);
    }
    // Tensor-core Hilbert attention (1-term S and PV)
    {
        dim3 grid(NSEGc, Hc, Bc);
        attn_kernel<<<grid, 256, ATT_SMEM>>>(hmap);
    }
    // Output projection (2-term on attention activations)
    {
        dim3 grid(HIDc / 128, (Bc * Mc) / 128);         // (8, 128)
        tgemm_kernel<1, 2><<<grid, 256, GEMM_SMEM>>>(ahi, alo, woh, out);
    }
}

// round 11
// speedup vs baseline: 8.7571x; 1.2453x over previous
#include <cuda_runtime.h>
#include <cuda_fp16.h>
#include <cstdint>

// Problem constants
#define Bc    4
#define Mc    4096
#define HIDc  1024
#define Hc    16
#define HDc   64
#define NSEGc 32
#define SCALEc 0.125f

// ---------------------------------------------------------------------------
// Static device scratch (allocation-free per harness rules)
// ---------------------------------------------------------------------------
__device__ __half g_qkv_hi[(size_t)3 * Bc * Hc * Mc * HDc];  // [c][b][h][m][d]
__device__ __half g_xhi[(size_t)Bc * Mc * HIDc];
__device__ __half g_wqkv_hi[(size_t)3 * HIDc * HIDc];
__device__ __half g_wout_hi[(size_t)HIDc * HIDc];
__device__ __half g_attn_hi[(size_t)Bc * Mc * HIDc];

// ===========================================================================
// Helpers
// ===========================================================================
__device__ __forceinline__ uint32_t smem_u32(const void* p) {
    uint32_t a;
    asm("{ .reg .u64 t; cvta.to.shared.u64 t, %1; cvt.u32.u64 %0, t; }"
        : "=r"(a) : "l"(p));
    return a;
}

__device__ __forceinline__ void ldsm_x4(uint32_t* r, uint32_t addr) {
    asm volatile("ldmatrix.sync.aligned.m8n8.x4.shared.b16 {%0,%1,%2,%3}, [%4];"
                 : "=r"(r[0]), "=r"(r[1]), "=r"(r[2]), "=r"(r[3]) : "r"(addr));
}
__device__ __forceinline__ void ldsm_x4_t(uint32_t* r, uint32_t addr) {
    asm volatile("ldmatrix.sync.aligned.m8n8.x4.trans.shared.b16 {%0,%1,%2,%3}, [%4];"
                 : "=r"(r[0]), "=r"(r[1]), "=r"(r[2]), "=r"(r[3]) : "r"(addr));
}

__device__ __forceinline__ void mma_f16(float* c, const uint32_t* a,
                                        uint32_t b0, uint32_t b1) {
    asm volatile(
        "mma.sync.aligned.m16n8k16.row.col.f32.f16.f16.f32 "
        "{%0,%1,%2,%3}, {%4,%5,%6,%7}, {%8,%9}, {%0,%1,%2,%3};"
        : "+f"(c[0]), "+f"(c[1]), "+f"(c[2]), "+f"(c[3])
        : "r"(a[0]), "r"(a[1]), "r"(a[2]), "r"(a[3]), "r"(b0), "r"(b1));
}

__device__ __forceinline__ void cp_async16(uint32_t dst, const void* src) {
    asm volatile("cp.async.cg.shared.global [%0], [%1], 16;"
                 :: "r"(dst), "l"(src) : "memory");
}
#define CP_COMMIT() asm volatile("cp.async.commit_group;" ::: "memory")
#define CP_WAIT0()  asm volatile("cp.async.wait_group 0;" ::: "memory")
#define CP_WAIT1()  asm volatile("cp.async.wait_group 1;" ::: "memory")

__device__ __forceinline__ uint32_t pack_f16(float x, float y) {
    __half2 v = __halves2half2(__float2half_rn(x), __float2half_rn(y));
    return *reinterpret_cast<uint32_t*>(&v);
}

// ===========================================================================
// Pre-split kernel: fp32 -> fp16
// ===========================================================================
__global__ __launch_bounds__(256) void split_kernel(const float* __restrict__ src,
                                                    __half* __restrict__ hi,
                                                    int n4) {
    const int i = blockIdx.x * 256 + threadIdx.x;
    if (i >= n4) return;
    const float4 v = ((const float4*)src)[i];
    ((__half2*)hi)[2 * i]     = __halves2half2(__float2half_rn(v.x), __float2half_rn(v.y));
    ((__half2*)hi)[2 * i + 1] = __halves2half2(__float2half_rn(v.z), __float2half_rn(v.w));
}

// ===========================================================================
// fp16 1-term tensor GEMM: C = Ahi·Whi^T.
// 128x128 tile, K-chunk 64 (128 B rows, stride 144 B -> conflict-free),
// 256 threads, warps 4(m) x 2(n); 3-stage cp.async, 2 tiles/stage.
// Barrier every 64 MMAs (4 k16 steps per iteration).
// MODE 0: epilogue scatters fp16 into g_qkv_hi.  MODE 1: fp32 row-major out.
// ===========================================================================
#define TK        64
#define NITER     (HIDc / TK)              // 16
#define LDSTR     72                       // fp16 elems per SMEM row (144 B)
#define TILE_HB   (128 * LDSTR * 2)        // 18432 B
#define STAGE_B   (2 * TILE_HB)            // 36864 B (A, B)
#define GEMM_SMEM (3 * STAGE_B)            // 110592 B

template <int MODE>
__global__ __launch_bounds__(256, 2) void tgemm_kernel(
        const __half* __restrict__ Ahi_g, const __half* __restrict__ Bhi_g,
        float* __restrict__ Cout) {
    extern __shared__ __align__(16) char smraw[];
    const uint32_t smb = smem_u32(smraw);

    const int tid  = threadIdx.x;
    const int wid  = tid >> 5;
    const int lane = tid & 31;
    const int row0 = blockIdx.y * 128;
    const int col0 = blockIdx.x * 128;
    const int warp_m = wid & 3;
    const int warp_n = wid >> 2;

    // ---- cp.async streams: 8 per thread (2 tiles x 4 chunks) ----
    const __half* src[8];
    uint32_t rel[8];
#pragma unroll
    for (int t = 0; t < 4; t++) {
        const int ci  = tid + 256 * t;
        const int row = ci >> 3;            // 0..127
        const int c16 = ci & 7;             // 16B chunk within 64-elem row
        const size_t offA = (size_t)(row0 + row) * HIDc + c16 * 8;
        const size_t offB = (size_t)(col0 + row) * HIDc + c16 * 8;
        const uint32_t so = (uint32_t)(row * (LDSTR * 2) + c16 * 16);
        src[2 * t + 0] = Ahi_g + offA;  rel[2 * t + 0] = so;
        src[2 * t + 1] = Bhi_g + offB;  rel[2 * t + 1] = TILE_HB + so;
    }

    const int sub = lane >> 3;
    const int r8  = lane & 7;
    uint32_t a_lm[2], b_lm[4];
#pragma unroll
    for (int mt = 0; mt < 2; mt++) {
        const int row = warp_m * 32 + mt * 16 + (sub & 1) * 8 + r8;
        a_lm[mt] = smb + row * (LDSTR * 2) + (sub >> 1) * 16;
    }
#pragma unroll
    for (int np = 0; np < 4; np++) {
        const int row = warp_n * 64 + np * 16 + (sub >> 1) * 8 + r8;
        b_lm[np] = smb + TILE_HB + row * (LDSTR * 2) + (sub & 1) * 16;
    }

    float acc[2][8][4];
#pragma unroll
    for (int i = 0; i < 2; i++)
#pragma unroll
        for (int j = 0; j < 8; j++)
#pragma unroll
            for (int q = 0; q < 4; q++) acc[i][j][q] = 0.0f;

    // ---- prologue: stages 0 and 1 ----
#pragma unroll
    for (int j = 0; j < 8; j++) cp_async16(smb + rel[j], src[j]);
    CP_COMMIT();
#pragma unroll
    for (int j = 0; j < 8; j++) {
        src[j] += TK;
        cp_async16(smb + STAGE_B + rel[j], src[j]);
    }
    CP_COMMIT();

    for (int it = 0; it < NITER; it++) {
        if (it + 1 < NITER) { CP_WAIT1(); } else { CP_WAIT0(); }
        __syncthreads();
        const uint32_t stg = (uint32_t)(it % 3) * STAGE_B;

        if (it + 2 < NITER) {
            const uint32_t nst = smb + (uint32_t)((it + 2) % 3) * STAGE_B;
#pragma unroll
            for (int j = 0; j < 8; j++) {
                src[j] += TK;
                cp_async16(nst + rel[j], src[j]);
            }
            CP_COMMIT();
        }

#pragma unroll
        for (int k16 = 0; k16 < 4; k16++) {
            const uint32_t kb = stg + k16 * 32;
            uint32_t Ah[2][4], Bf[4][4];
#pragma unroll
            for (int mt = 0; mt < 2; mt++) ldsm_x4(Ah[mt], a_lm[mt] + kb);
#pragma unroll
            for (int np = 0; np < 4; np++) ldsm_x4(Bf[np], b_lm[np] + kb);
#pragma unroll
            for (int mt = 0; mt < 2; mt++)
#pragma unroll
                for (int np = 0; np < 4; np++) {
                    mma_f16(acc[mt][2 * np],     Ah[mt], Bf[np][0], Bf[np][1]);
                    mma_f16(acc[mt][2 * np + 1], Ah[mt], Bf[np][2], Bf[np][3]);
                }
        }
    }

    // ---- epilogue ----
    const int rbase = row0 + warp_m * 32 + (lane >> 2);
    const int cbase = col0 + warp_n * 64 + 2 * (lane & 3);
#pragma unroll
    for (int mt = 0; mt < 2; mt++) {
#pragma unroll
        for (int nt = 0; nt < 8; nt++) {
            const int c = cbase + nt * 8;
#pragma unroll
            for (int half = 0; half < 2; half++) {
                const int r = rbase + mt * 16 + half * 8;
                const float vx = acc[mt][nt][2 * half];
                const float vy = acc[mt][nt][2 * half + 1];
                if (MODE == 0) {
                    const int b  = r >> 12;
                    const int m  = r & 4095;
                    const int cc = c >> 10;
                    const int h  = (c & 1023) >> 6;
                    const int d  = c & 63;
                    const size_t idx = (size_t)cc * (Bc * Hc * Mc * HDc) +
                        (((size_t)b * Hc + h) * Mc + m) * HDc + d;
                    *(uint32_t*)&g_qkv_hi[idx] = pack_f16(vx, vy);
                } else {
                    *(float2*)&Cout[(size_t)r * HIDc + c] = make_float2(vx, vy);
                }
            }
        }
    }
}

// ===========================================================================
// Tensor-core attention (fp16 1-term): one block per (seg,h,b), 8 warps.
// S = Qh·Kh^T, in-register masked softmax, out = Ph·Vh.
// SMEM: gather Qh@0, Kh@18432, Vh@36864.
//       P overlay: Ph@0 (stride 272B, 34816 B, over Qh/Kh after S-phase).
// ===========================================================================
#define ATT_SMEM 55296

__global__ __launch_bounds__(256, 2) void attn_kernel(const int* __restrict__ hmap) {
    const int seg = blockIdx.x;
    const int h   = blockIdx.y;
    const int b   = blockIdx.z;

    extern __shared__ __align__(16) char smraw[];
    const uint32_t smb = smem_u32(smraw);
    __shared__ int toks[128];

    const int tid  = threadIdx.x;
    const int warp = tid >> 5;
    const int lane = tid & 31;

    if (tid < 128) toks[tid] = hmap[seg * 128 + tid];
    __syncthreads();

    // ---- gather: 3 parts (Qh,Kh,Vh) x 128 rows x 8 x 16B ----
#pragma unroll
    for (int n = 0; n < 12; n++) {
        const int c   = tid + 256 * n;
        const int p   = c >> 10;              // 0=Q, 1=K, 2=V
        const int rem = c & 1023;
        const int row = rem >> 3;
        const int ch  = rem & 7;
        const __half* s = g_qkv_hi + (size_t)p * (Bc * Hc * Mc * HDc) +
            (((size_t)b * Hc + h) * Mc + toks[row]) * HDc + ch * 8;
        cp_async16(smb + (uint32_t)p * 18432u + (uint32_t)(row * 144 + ch * 16), s);
    }
    CP_COMMIT();
    CP_WAIT0();
    __syncthreads();

    const int w16 = warp * 16;
    const int sub = lane >> 3;
    const int r8  = lane & 7;

    // ---- S = Qh Kh^T ----
    const uint32_t aq = smb + (uint32_t)((w16 + (sub & 1) * 8 + r8) * 144 + (sub >> 1) * 16);
    uint32_t bk[8];
#pragma unroll
    for (int np = 0; np < 8; np++)
        bk[np] = smb + 18432u + (uint32_t)((np * 16 + (sub >> 1) * 8 + r8) * 144 + (sub & 1) * 16);

    float s_acc[16][4];
#pragma unroll
    for (int j = 0; j < 16; j++)
#pragma unroll
        for (int q = 0; q < 4; q++) s_acc[j][q] = 0.0f;

#pragma unroll
    for (int kt = 0; kt < 4; kt++) {
        const uint32_t kb = kt * 32;
        uint32_t Ah[4], Bf[8][4];
        ldsm_x4(Ah, aq + kb);
#pragma unroll
        for (int np = 0; np < 8; np++) ldsm_x4(Bf[np], bk[np] + kb);
#pragma unroll
        for (int np = 0; np < 8; np++) {
            mma_f16(s_acc[2 * np],     Ah, Bf[np][0], Bf[np][1]);
            mma_f16(s_acc[2 * np + 1], Ah, Bf[np][2], Bf[np][3]);
        }
    }

    // ---- masked softmax in fragment registers ----
    const bool oddrow = ((lane >> 2) & 1) != 0;
    float mx0 = -1e30f, mx1 = -1e30f;
#pragma unroll
    for (int j = 0; j < 16; j++) {
#pragma unroll
        for (int q = 0; q < 4; q++) s_acc[j][q] *= SCALEc;
        if (oddrow) { s_acc[j][1] = -1e30f; s_acc[j][3] = -1e30f; }
        mx0 = fmaxf(mx0, fmaxf(s_acc[j][0], s_acc[j][1]));
        mx1 = fmaxf(mx1, fmaxf(s_acc[j][2], s_acc[j][3]));
    }
    mx0 = fmaxf(mx0, __shfl_xor_sync(0xffffffffu, mx0, 1));
    mx0 = fmaxf(mx0, __shfl_xor_sync(0xffffffffu, mx0, 2));
    mx1 = fmaxf(mx1, __shfl_xor_sync(0xffffffffu, mx1, 1));
    mx1 = fmaxf(mx1, __shfl_xor_sync(0xffffffffu, mx1, 2));

    float sum0 = 0.f, sum1 = 0.f;
#pragma unroll
    for (int j = 0; j < 16; j++) {
        s_acc[j][0] = __expf(s_acc[j][0] - mx0);
        s_acc[j][1] = __expf(s_acc[j][1] - mx0);
        s_acc[j][2] = __expf(s_acc[j][2] - mx1);
        s_acc[j][3] = __expf(s_acc[j][3] - mx1);
        sum0 += s_acc[j][0] + s_acc[j][1];
        sum1 += s_acc[j][2] + s_acc[j][3];
    }
    sum0 += __shfl_xor_sync(0xffffffffu, sum0, 1);
    sum0 += __shfl_xor_sync(0xffffffffu, sum0, 2);
    sum1 += __shfl_xor_sync(0xffffffffu, sum1, 1);
    sum1 += __shfl_xor_sync(0xffffffffu, sum1, 2);
    const float inv0 = 1.0f / sum0;
    const float inv1 = 1.0f / sum1;

    __syncthreads();   // all warps done reading Q/K before P overlay writes

    // ---- store Ph into overlay (stride 272B) ----
    const uint32_t prow = smb + (uint32_t)((w16 + (lane >> 2)) * 272 + (lane & 3) * 4);
#pragma unroll
    for (int j = 0; j < 16; j++) {
        const float p0 = s_acc[j][0] * inv0, p1 = s_acc[j][1] * inv0;
        const float p2 = s_acc[j][2] * inv1, p3 = s_acc[j][3] * inv1;
        const uint32_t o0 = prow + j * 16;
        const uint32_t o1 = o0 + 8 * 272;
        asm volatile("st.shared.b32 [%0], %1;" :: "r"(o0), "r"(pack_f16(p0, p1)) : "memory");
        asm volatile("st.shared.b32 [%0], %1;" :: "r"(o1), "r"(pack_f16(p2, p3)) : "memory");
    }
    __syncthreads();   // P visible to ldmatrix across the block

    // ---- out = Ph · Vh ----
    const uint32_t ap = smb + (uint32_t)((w16 + (lane & 15)) * 272 + (lane >> 4) * 16);
    const int mat = lane >> 3;
    const uint32_t vb = smb + 36864u +
        (uint32_t)(((mat & 1) * 8 + (lane & 7)) * 144 + (mat >> 1) * 16);

    float o_acc[8][4];
#pragma unroll
    for (int j = 0; j < 8; j++)
#pragma unroll
        for (int q = 0; q < 4; q++) o_acc[j][q] = 0.0f;

#pragma unroll
    for (int kt = 0; kt < 8; kt++) {
        uint32_t Ph[4], Vf[4][4];
        ldsm_x4(Ph, ap + kt * 32);
#pragma unroll
        for (int vp = 0; vp < 4; vp++)
            ldsm_x4_t(Vf[vp], vb + (uint32_t)kt * 2304u + vp * 32u);
#pragma unroll
        for (int vp = 0; vp < 4; vp++) {
            mma_f16(o_acc[2 * vp],     Ph, Vf[vp][0], Vf[vp][1]);
            mma_f16(o_acc[2 * vp + 1], Ph, Vf[vp][2], Vf[vp][3]);
        }
    }

    // ---- epilogue: write fp16 attention output ----
    const int r0 = w16 + (lane >> 2);
    const size_t row0g = ((size_t)b * Mc + (size_t)seg * 128 + r0) * HIDc + h * 64;
    const size_t row1g = row0g + 8 * HIDc;
    const int dbase = 2 * (lane & 3);
#pragma unroll
    for (int j = 0; j < 8; j++) {
        const int d = 8 * j + dbase;
        *(uint32_t*)&g_attn_hi[row0g + d] = pack_f16(o_acc[j][0], o_acc[j][1]);
        *(uint32_t*)&g_attn_hi[row1g + d] = pack_f16(o_acc[j][2], o_acc[j][3]);
    }
}

// ===========================================================================
extern "C" void kernel_launch(void* const* d_in, const int* in_sizes, int n_in,
                              void* d_out, int out_size) {
    const float* x     = (const float*)d_in[0];
    const float* w_qkv = (const float*)d_in[1];
    const float* w_out = (const float*)d_in[2];
    const int*   hmap  = (const int*)d_in[3];
    float*       out   = (float*)d_out;

    cudaFuncSetAttribute(tgemm_kernel<0>, cudaFuncAttributeMaxDynamicSharedMemorySize, GEMM_SMEM);
    cudaFuncSetAttribute(tgemm_kernel<1>, cudaFuncAttributeMaxDynamicSharedMemorySize, GEMM_SMEM);
    cudaFuncSetAttribute(attn_kernel,     cudaFuncAttributeMaxDynamicSharedMemorySize, ATT_SMEM);

    __half *xhi, *wqh, *woh, *ahi;
    cudaGetSymbolAddress((void**)&xhi, g_xhi);
    cudaGetSymbolAddress((void**)&wqh, g_wqkv_hi);
    cudaGetSymbolAddress((void**)&woh, g_wout_hi);
    cudaGetSymbolAddress((void**)&ahi, g_attn_hi);

    // Pre-split: all inputs -> fp16
    {
        int n4 = (Bc * Mc * HIDc) / 4;
        split_kernel<<<(n4 + 255) / 256, 256>>>(x, xhi, n4);
        n4 = (3 * HIDc * HIDc) / 4;
        split_kernel<<<(n4 + 255) / 256, 256>>>(w_qkv, wqh, n4);
        n4 = (HIDc * HIDc) / 4;
        split_kernel<<<(n4 + 255) / 256, 256>>>(w_out, woh, n4);
    }
    // QKV projection: 1-term, all 3072 columns
    {
        dim3 grid(3072 / 128, (Bc * Mc) / 128);         // (24, 128)
        tgemm_kernel<0><<<grid, 256, GEMM_SMEM>>>(xhi, wqh, nullptr);
    }
    // Tensor-core Hilbert attention (1-term)
    {
        dim3 grid(NSEGc, Hc, Bc);
        attn_kernel<<<grid, 256, ATT_SMEM>>>(hmap);
    }
    // Output projection: 1-term
    {
        dim3 grid(HIDc / 128, (Bc * Mc) / 128);         // (8, 128)
        tgemm_kernel<1><<<grid, 256, GEMM_SMEM>>>(ahi, woh, out);
    }
}